// round 2
// baseline (speedup 1.0000x reference)
#include <cuda_runtime.h>
#include <cstdint>

#define T_TOKENS 4096
#define H_DIM    2048
#define I_DIM    1408
#define E_NUM    16
#define SI_DIM   2816
#define SLOTS    8192   // T * TOP_K

// ---------------- scratch (device globals; no runtime allocation) ----------
__device__ int   g_cnt[E_NUM];
__device__ int   g_off[E_NUM];
__device__ int   g_cur[E_NUM];
__device__ int   g_eid[T_TOKENS * 2];
__device__ float g_wgt[T_TOKENS * 2];
__device__ int   g_slot[T_TOKENS * 2];
__device__ int   g_rowtok[SLOTS];
// 8192*1408 == 4096*2816 == 11534336 floats; reused by shared (Gs/Us) then routed (G/U)
__device__ float g_bufG[SLOTS * I_DIM];
__device__ float g_bufU[SLOTS * I_DIM];
__device__ float g_Y[SLOTS * H_DIM];

// ---------------- threefry2x32 core (verified vs Random123 KAT) -------------
__device__ __forceinline__ uint32_t rotl32(uint32_t v, int r) {
    return (v << r) | (v >> (32 - r));
}

__device__ __forceinline__ void threefry2x32(uint32_t x0, uint32_t x1,
                                             uint32_t& o0, uint32_t& o1) {
    const uint32_t ks0 = 0u, ks1 = 42u, ks2 = 0u ^ 42u ^ 0x1BD11BDAu;
    x0 += ks0; x1 += ks1;
    // block 0: rotations [13,15,26,6]
    x0 += x1; x1 = rotl32(x1, 13); x1 ^= x0;
    x0 += x1; x1 = rotl32(x1, 15); x1 ^= x0;
    x0 += x1; x1 = rotl32(x1, 26); x1 ^= x0;
    x0 += x1; x1 = rotl32(x1, 6);  x1 ^= x0;
    x0 += ks1; x1 += ks2 + 1u;
    // block 1: rotations [17,29,16,24]
    x0 += x1; x1 = rotl32(x1, 17); x1 ^= x0;
    x0 += x1; x1 = rotl32(x1, 29); x1 ^= x0;
    x0 += x1; x1 = rotl32(x1, 16); x1 ^= x0;
    x0 += x1; x1 = rotl32(x1, 24); x1 ^= x0;
    x0 += ks2; x1 += ks0 + 2u;
    // block 2
    x0 += x1; x1 = rotl32(x1, 13); x1 ^= x0;
    x0 += x1; x1 = rotl32(x1, 15); x1 ^= x0;
    x0 += x1; x1 = rotl32(x1, 26); x1 ^= x0;
    x0 += x1; x1 = rotl32(x1, 6);  x1 ^= x0;
    x0 += ks0; x1 += ks1 + 3u;
    // block 3
    x0 += x1; x1 = rotl32(x1, 17); x1 ^= x0;
    x0 += x1; x1 = rotl32(x1, 29); x1 ^= x0;
    x0 += x1; x1 = rotl32(x1, 16); x1 ^= x0;
    x0 += x1; x1 = rotl32(x1, 24); x1 ^= x0;
    x0 += ks1; x1 += ks2 + 4u;
    // block 4
    x0 += x1; x1 = rotl32(x1, 13); x1 ^= x0;
    x0 += x1; x1 = rotl32(x1, 15); x1 ^= x0;
    x0 += x1; x1 = rotl32(x1, 26); x1 ^= x0;
    x0 += x1; x1 = rotl32(x1, 6);  x1 ^= x0;
    x0 += ks2; x1 += ks0 + 5u;
    o0 = x0; o1 = x1;
}

// XLA/CHLO erf_inv for f32 (Giles), w = -log1p(-x*x)
__device__ __forceinline__ float erfinv_xla(float x) {
    float w = -log1pf(-x * x);
    float p;
    if (w < 5.0f) {
        w -= 2.5f;
        p = 2.81022636e-08f;
        p = fmaf(p, w, 3.43273939e-07f);
        p = fmaf(p, w, -3.5233877e-06f);
        p = fmaf(p, w, -4.39150654e-06f);
        p = fmaf(p, w, 0.00021858087f);
        p = fmaf(p, w, -0.00125372503f);
        p = fmaf(p, w, -0.00417768164f);
        p = fmaf(p, w, 0.246640727f);
        p = fmaf(p, w, 1.50140941f);
    } else {
        w = sqrtf(w) - 3.0f;
        p = -0.000200214257f;
        p = fmaf(p, w, 0.000100950558f);
        p = fmaf(p, w, 0.00134934322f);
        p = fmaf(p, w, -0.00367342844f);
        p = fmaf(p, w, 0.00573950773f);
        p = fmaf(p, w, -0.0076224613f);
        p = fmaf(p, w, 0.00943887047f);
        p = fmaf(p, w, 1.00167406f);
        p = fmaf(p, w, 2.83297682f);
    }
    return p * x;
}

// ---------------- routing kernels ------------------------------------------
__global__ void zero_kernel() {
    if (threadIdx.x < E_NUM) g_cnt[threadIdx.x] = 0;
}

__global__ void route_kernel() {
    int t = blockIdx.x * blockDim.x + threadIdx.x;
    if (t >= T_TOKENS) return;
    float s[E_NUM];
#pragma unroll
    for (int e = 0; e < E_NUM; ++e) {
        uint32_t i = (uint32_t)t * E_NUM + (uint32_t)e;
        // jax_threefry_partitionable (default True in modern JAX):
        // per-element counter = 64-bit linear index -> (hi, lo) = (0, i);
        // 32-bit draw folds the two outputs: bits = o0 ^ o1.
        uint32_t o0, o1;
        threefry2x32(0u, i, o0, o1);
        uint32_t bits = o0 ^ o1;
        // JAX uniform on [nextafter(-1,0), 1): bits>>9 | 1.0f bit-trick
        float u01 = __uint_as_float((bits >> 9) | 0x3f800000u) - 1.0f;
        float u = fmaf(u01, 2.0f, -0.99999994f);   // span (1 - minval) rounds to 2.0f
        u = fmaxf(-0.99999994f, u);
        float nz = 1.4142135381698608f * erfinv_xla(u);   // float32(sqrt(2))
        s[e] = 1.0f / (1.0f + expf(-nz));
    }
    int b0 = 0;
#pragma unroll
    for (int e = 1; e < E_NUM; ++e) if (s[e] > s[b0]) b0 = e;
    int b1 = (b0 == 0) ? 1 : 0;
#pragma unroll
    for (int e = 0; e < E_NUM; ++e) if (e != b0 && s[e] > s[b1]) b1 = e;
    float sum = s[b0] + s[b1] + 1e-8f;
    g_eid[2 * t + 0] = b0;
    g_eid[2 * t + 1] = b1;
    g_wgt[2 * t + 0] = s[b0] / sum;
    g_wgt[2 * t + 1] = s[b1] / sum;
    atomicAdd(&g_cnt[b0], 1);
    atomicAdd(&g_cnt[b1], 1);
}

__global__ void scan_kernel() {
    int a = 0;
    for (int e = 0; e < E_NUM; ++e) { g_off[e] = a; g_cur[e] = a; a += g_cnt[e]; }
}

__global__ void scatter_kernel() {
    int t = blockIdx.x * blockDim.x + threadIdx.x;
    if (t >= T_TOKENS) return;
#pragma unroll
    for (int k = 0; k < 2; ++k) {
        int e = g_eid[2 * t + k];
        int sidx = atomicAdd(&g_cur[e], 1);
        g_slot[2 * t + k] = sidx;
        g_rowtok[sidx] = t;
    }
}

// ---------------- packed f32x2 helpers --------------------------------------
typedef unsigned long long u64t;

__device__ __forceinline__ u64t pack2dup(float a) {
    u64t r;
    asm("mov.b64 %0, {%1, %1};" : "=l"(r) : "f"(a));
    return r;
}
__device__ __forceinline__ void fma2(u64t& acc, u64t a, u64t b) {
    asm("fma.rn.f32x2 %0, %1, %2, %0;" : "+l"(acc) : "l"(a), "l"(b));
}
__device__ __forceinline__ float2 unpack2(u64t v) {
    float2 r;
    asm("mov.b64 {%0, %1}, %2;" : "=f"(r.x), "=f"(r.y) : "l"(v));
    return r;
}

__device__ __forceinline__ float swiglu_f(float g, float u) {
    return (g / (1.0f + expf(-g))) * u;
}

// ---------------- generic 128x128x8 SGEMM -----------------------------------
// mode bit0: A = swiglu(A0, A1) elementwise   (A rows indexed directly)
// mode bit1: routed (M = g_cnt[z], seg = g_off[z], B += z*K*N)
// mode bit2: gather A rows via g_rowtok[seg+m]
__global__ void __launch_bounds__(256) sgemm128(
    const float* __restrict__ A0, const float* __restrict__ A1,
    const float* __restrict__ Bmat, float* __restrict__ C,
    int N, int K, int fixedM, int mode)
{
    const bool doSw   = (mode & 1) != 0;
    const bool routed = (mode & 2) != 0;
    const bool gather = (mode & 4) != 0;

    int e = blockIdx.z;
    int M, seg;
    const float* B = Bmat;
    if (routed) {
        M = g_cnt[e]; seg = g_off[e];
        B += (size_t)e * (size_t)K * (size_t)N;
    } else { M = fixedM; seg = 0; }

    int mbase = blockIdx.y * 128;
    if (mbase >= M) return;
    int nbase = blockIdx.x * 128;

    __shared__ float As[2][8][128];
    __shared__ float Bs[2][8][128];

    int tid  = threadIdx.x;
    int aRow = tid >> 1;            // 0..127
    int aK   = (tid & 1) * 4;       // 0 or 4
    int bK   = tid >> 5;            // 0..7
    int bN   = (tid & 31) * 4;      // 0..124

    int m = mbase + aRow;
    bool mv = (m < M);
    const float* aP0 = A0;
    const float* aP1 = A1;
    if (mv) {
        int r = seg + m;
        int src = gather ? g_rowtok[r] : r;
        aP0 = A0 + (size_t)src * K + aK;
        aP1 = A1 + (size_t)src * K + aK;
    }
    const float* bP = B + (size_t)bK * N + nbase + bN;

    float4 aF = make_float4(0.f, 0.f, 0.f, 0.f);
    float4 aG = make_float4(0.f, 0.f, 0.f, 0.f);
    float4 bF;

    if (mv) {
        aF = *(const float4*)(aP0);
        if (doSw) aG = *(const float4*)(aP1);
    }
    bF = *(const float4*)(bP);

    {
        float v0 = aF.x, v1 = aF.y, v2 = aF.z, v3 = aF.w;
        if (doSw) {
            v0 = swiglu_f(aF.x, aG.x); v1 = swiglu_f(aF.y, aG.y);
            v2 = swiglu_f(aF.z, aG.z); v3 = swiglu_f(aF.w, aG.w);
        }
        As[0][aK + 0][aRow] = v0; As[0][aK + 1][aRow] = v1;
        As[0][aK + 2][aRow] = v2; As[0][aK + 3][aRow] = v3;
        *(float4*)&Bs[0][bK][bN] = bF;
    }
    __syncthreads();

    u64t acc[8][4];
#pragma unroll
    for (int i = 0; i < 8; ++i)
#pragma unroll
        for (int j = 0; j < 4; ++j) acc[i][j] = 0ull;

    int row0 = (tid >> 4) * 8;
    int col0 = (tid & 15) * 8;

    int nk = K >> 3;
    int buf = 0;
    for (int kt = 0; kt < nk; ++kt) {
        bool more = (kt + 1) < nk;
        if (more) {
            if (mv) {
                aF = *(const float4*)(aP0 + (kt + 1) * 8);
                if (doSw) aG = *(const float4*)(aP1 + (kt + 1) * 8);
            }
            bF = *(const float4*)(bP + (size_t)(kt + 1) * 8 * N);
        }
#pragma unroll
        for (int kk = 0; kk < 8; ++kk) {
            float a[8];
            *(float4*)&a[0] = *(const float4*)&As[buf][kk][row0];
            *(float4*)&a[4] = *(const float4*)&As[buf][kk][row0 + 4];
            ulonglong2 blo = *(const ulonglong2*)&Bs[buf][kk][col0];
            ulonglong2 bhi = *(const ulonglong2*)&Bs[buf][kk][col0 + 4];
            u64t b2[4];
            b2[0] = blo.x; b2[1] = blo.y; b2[2] = bhi.x; b2[3] = bhi.y;
#pragma unroll
            for (int i = 0; i < 8; ++i) {
                u64t a2 = pack2dup(a[i]);
#pragma unroll
                for (int j = 0; j < 4; ++j) fma2(acc[i][j], a2, b2[j]);
            }
        }
        if (more) {
            int nb = buf ^ 1;
            float v0 = aF.x, v1 = aF.y, v2 = aF.z, v3 = aF.w;
            if (doSw) {
                v0 = swiglu_f(aF.x, aG.x); v1 = swiglu_f(aF.y, aG.y);
                v2 = swiglu_f(aF.z, aG.z); v3 = swiglu_f(aF.w, aG.w);
            }
            As[nb][aK + 0][aRow] = v0; As[nb][aK + 1][aRow] = v1;
            As[nb][aK + 2][aRow] = v2; As[nb][aK + 3][aRow] = v3;
            *(float4*)&Bs[nb][bK][bN] = bF;
        }
        __syncthreads();
        buf ^= 1;
    }

#pragma unroll
    for (int i = 0; i < 8; ++i) {
        int mm = mbase + row0 + i;
        if (mm < M) {
            float* cp = C + (size_t)(seg + mm) * N + nbase + col0;
            float2 p0 = unpack2(acc[i][0]);
            float2 p1 = unpack2(acc[i][1]);
            float2 p2 = unpack2(acc[i][2]);
            float2 p3 = unpack2(acc[i][3]);
            *(float4*)cp       = make_float4(p0.x, p0.y, p1.x, p1.y);
            *(float4*)(cp + 4) = make_float4(p2.x, p2.y, p3.x, p3.y);
        }
    }
}

// ---------------- combine: out += w0*Y[slot0] + w1*Y[slot1] ------------------
__global__ void combine_kernel(float* __restrict__ out) {
    int t = blockIdx.y;
    int c = (blockIdx.x * blockDim.x + threadIdx.x) * 4;
    int s0 = g_slot[2 * t + 0], s1 = g_slot[2 * t + 1];
    float w0 = g_wgt[2 * t + 0], w1 = g_wgt[2 * t + 1];
    const float4 y0 = *(const float4*)&g_Y[(size_t)s0 * H_DIM + c];
    const float4 y1 = *(const float4*)&g_Y[(size_t)s1 * H_DIM + c];
    float4 o = *(float4*)&out[(size_t)t * H_DIM + c];
    o.x += w0 * y0.x + w1 * y1.x;
    o.y += w0 * y0.y + w1 * y1.y;
    o.z += w0 * y0.z + w1 * y1.z;
    o.w += w0 * y0.w + w1 * y1.w;
    *(float4*)&out[(size_t)t * H_DIM + c] = o;
}

// ---------------- launch -----------------------------------------------------
extern "C" void kernel_launch(void* const* d_in, const int* in_sizes, int n_in,
                              void* d_out, int out_size) {
    (void)in_sizes; (void)n_in; (void)out_size;
    const float* x      = (const float*)d_in[0];
    // d_in[1] router_w, d_in[2] router_b: dead inputs (RandomSTE forward = noise)
    const float* w_gate = (const float*)d_in[3];
    const float* w_up   = (const float*)d_in[4];
    const float* w_down = (const float*)d_in[5];
    const float* sg     = (const float*)d_in[6];
    const float* su     = (const float*)d_in[7];
    const float* sd     = (const float*)d_in[8];
    float* out = (float*)d_out;

    void *pG = nullptr, *pU = nullptr, *pY = nullptr;
    cudaGetSymbolAddress(&pG, g_bufG);
    cudaGetSymbolAddress(&pU, g_bufU);
    cudaGetSymbolAddress(&pY, g_Y);
    float* bG = (float*)pG;
    float* bU = (float*)pU;
    float* Y  = (float*)pY;

    // routing
    zero_kernel<<<1, 32>>>();
    route_kernel<<<T_TOKENS / 256, 256>>>();
    scan_kernel<<<1, 1>>>();
    scatter_kernel<<<T_TOKENS / 256, 256>>>();

    // shared expert: Gs, Us = x @ sg, x @ su ; out = swiglu(Gs,Us) @ sd
    sgemm128<<<dim3(SI_DIM / 128, T_TOKENS / 128, 1), 256>>>(
        x, x, sg, bG, SI_DIM, H_DIM, T_TOKENS, 0);
    sgemm128<<<dim3(SI_DIM / 128, T_TOKENS / 128, 1), 256>>>(
        x, x, su, bU, SI_DIM, H_DIM, T_TOKENS, 0);
    sgemm128<<<dim3(H_DIM / 128, T_TOKENS / 128, 1), 256>>>(
        bG, bU, sd, out, H_DIM, SI_DIM, T_TOKENS, 1);

    // routed experts (grouped, gathered): G,U per slot; Y = swiglu(G,U) @ w_down[e]
    sgemm128<<<dim3(I_DIM / 128, T_TOKENS / 128, E_NUM), 256>>>(
        x, x, w_gate, bG, I_DIM, H_DIM, 0, 2 | 4);
    sgemm128<<<dim3(I_DIM / 128, T_TOKENS / 128, E_NUM), 256>>>(
        x, x, w_up, bU, I_DIM, H_DIM, 0, 2 | 4);
    sgemm128<<<dim3(H_DIM / 128, T_TOKENS / 128, E_NUM), 256>>>(
        bG, bU, w_down, Y, H_DIM, I_DIM, 0, 2 | 1);

    // combine routed contributions into out
    combine_kernel<<<dim3(H_DIM / 1024, T_TOKENS), 256>>>(out);
}

// round 3
// speedup vs baseline: 1.0002x; 1.0002x over previous
#include <cuda_runtime.h>
#include <cstdint>

#define T_TOKENS 4096
#define H_DIM    2048
#define I_DIM    1408
#define E_NUM    16
#define SI_DIM   2816
#define SLOTS    8192   // T * TOP_K

// ---------------- scratch (device globals; no runtime allocation) ----------
__device__ int   g_cnt[E_NUM];
__device__ int   g_off[E_NUM];
__device__ int   g_cur[E_NUM];
__device__ int   g_eid[T_TOKENS * 2];
__device__ float g_wgt[T_TOKENS * 2];
__device__ int   g_slot[T_TOKENS * 2];
__device__ int   g_rowtok[SLOTS];
// 8192*1408 == 4096*2816 == 11534336 floats; reused by shared (Gs/Us) then routed (G/U)
__device__ float g_bufG[SLOTS * I_DIM];
__device__ float g_bufU[SLOTS * I_DIM];
__device__ float g_Y[SLOTS * H_DIM];

// ---------------- threefry2x32 core (verified vs Random123 KAT) -------------
__device__ __forceinline__ uint32_t rotl32(uint32_t v, int r) {
    return (v << r) | (v >> (32 - r));
}

__device__ __forceinline__ void threefry2x32(uint32_t x0, uint32_t x1,
                                             uint32_t& o0, uint32_t& o1) {
    const uint32_t ks0 = 0u, ks1 = 42u, ks2 = 0u ^ 42u ^ 0x1BD11BDAu;
    x0 += ks0; x1 += ks1;
    // block 0: rotations [13,15,26,6]
    x0 += x1; x1 = rotl32(x1, 13); x1 ^= x0;
    x0 += x1; x1 = rotl32(x1, 15); x1 ^= x0;
    x0 += x1; x1 = rotl32(x1, 26); x1 ^= x0;
    x0 += x1; x1 = rotl32(x1, 6);  x1 ^= x0;
    x0 += ks1; x1 += ks2 + 1u;
    // block 1: rotations [17,29,16,24]
    x0 += x1; x1 = rotl32(x1, 17); x1 ^= x0;
    x0 += x1; x1 = rotl32(x1, 29); x1 ^= x0;
    x0 += x1; x1 = rotl32(x1, 16); x1 ^= x0;
    x0 += x1; x1 = rotl32(x1, 24); x1 ^= x0;
    x0 += ks2; x1 += ks0 + 2u;
    // block 2
    x0 += x1; x1 = rotl32(x1, 13); x1 ^= x0;
    x0 += x1; x1 = rotl32(x1, 15); x1 ^= x0;
    x0 += x1; x1 = rotl32(x1, 26); x1 ^= x0;
    x0 += x1; x1 = rotl32(x1, 6);  x1 ^= x0;
    x0 += ks0; x1 += ks1 + 3u;
    // block 3
    x0 += x1; x1 = rotl32(x1, 17); x1 ^= x0;
    x0 += x1; x1 = rotl32(x1, 29); x1 ^= x0;
    x0 += x1; x1 = rotl32(x1, 16); x1 ^= x0;
    x0 += x1; x1 = rotl32(x1, 24); x1 ^= x0;
    x0 += ks1; x1 += ks2 + 4u;
    // block 4
    x0 += x1; x1 = rotl32(x1, 13); x1 ^= x0;
    x0 += x1; x1 = rotl32(x1, 15); x1 ^= x0;
    x0 += x1; x1 = rotl32(x1, 26); x1 ^= x0;
    x0 += x1; x1 = rotl32(x1, 6);  x1 ^= x0;
    x0 += ks2; x1 += ks0 + 5u;
    o0 = x0; o1 = x1;
}

// XLA/CHLO erf_inv for f32 (Giles), w = -log1p(-x*x)
__device__ __forceinline__ float erfinv_xla(float x) {
    float w = -log1pf(-x * x);
    float p;
    if (w < 5.0f) {
        w -= 2.5f;
        p = 2.81022636e-08f;
        p = fmaf(p, w, 3.43273939e-07f);
        p = fmaf(p, w, -3.5233877e-06f);
        p = fmaf(p, w, -4.39150654e-06f);
        p = fmaf(p, w, 0.00021858087f);
        p = fmaf(p, w, -0.00125372503f);
        p = fmaf(p, w, -0.00417768164f);
        p = fmaf(p, w, 0.246640727f);
        p = fmaf(p, w, 1.50140941f);
    } else {
        w = sqrtf(w) - 3.0f;
        p = -0.000200214257f;
        p = fmaf(p, w, 0.000100950558f);
        p = fmaf(p, w, 0.00134934322f);
        p = fmaf(p, w, -0.00367342844f);
        p = fmaf(p, w, 0.00573950773f);
        p = fmaf(p, w, -0.0076224613f);
        p = fmaf(p, w, 0.00943887047f);
        p = fmaf(p, w, 1.00167406f);
        p = fmaf(p, w, 2.83297682f);
    }
    return p * x;
}

// ---------------- routing kernels ------------------------------------------
__global__ void zero_kernel() {
    if (threadIdx.x < E_NUM) g_cnt[threadIdx.x] = 0;
}

__global__ void route_kernel() {
    int t = blockIdx.x * blockDim.x + threadIdx.x;
    if (t >= T_TOKENS) return;
    float s[E_NUM];
#pragma unroll
    for (int e = 0; e < E_NUM; ++e) {
        uint32_t i = (uint32_t)t * E_NUM + (uint32_t)e;
        // jax_threefry_partitionable (default True in modern JAX):
        // per-element counter = 64-bit linear index -> (hi, lo) = (0, i);
        // 32-bit draw folds the two outputs: bits = o0 ^ o1.
        uint32_t o0, o1;
        threefry2x32(0u, i, o0, o1);
        uint32_t bits = o0 ^ o1;
        // JAX uniform on [nextafter(-1,0), 1): bits>>9 | 1.0f bit-trick
        float u01 = __uint_as_float((bits >> 9) | 0x3f800000u) - 1.0f;
        float u = fmaf(u01, 2.0f, -0.99999994f);   // span (1 - minval) rounds to 2.0f
        u = fmaxf(-0.99999994f, u);
        float nz = 1.4142135381698608f * erfinv_xla(u);   // float32(sqrt(2))
        s[e] = 1.0f / (1.0f + expf(-nz));
    }
    int b0 = 0;
#pragma unroll
    for (int e = 1; e < E_NUM; ++e) if (s[e] > s[b0]) b0 = e;
    int b1 = (b0 == 0) ? 1 : 0;
#pragma unroll
    for (int e = 0; e < E_NUM; ++e) if (e != b0 && s[e] > s[b1]) b1 = e;
    float sum = s[b0] + s[b1] + 1e-8f;
    g_eid[2 * t + 0] = b0;
    g_eid[2 * t + 1] = b1;
    g_wgt[2 * t + 0] = s[b0] / sum;
    g_wgt[2 * t + 1] = s[b1] / sum;
    atomicAdd(&g_cnt[b0], 1);
    atomicAdd(&g_cnt[b1], 1);
}

__global__ void scan_kernel() {
    int a = 0;
    for (int e = 0; e < E_NUM; ++e) { g_off[e] = a; g_cur[e] = a; a += g_cnt[e]; }
}

__global__ void scatter_kernel() {
    int t = blockIdx.x * blockDim.x + threadIdx.x;
    if (t >= T_TOKENS) return;
#pragma unroll
    for (int k = 0; k < 2; ++k) {
        int e = g_eid[2 * t + k];
        int sidx = atomicAdd(&g_cur[e], 1);
        g_slot[2 * t + k] = sidx;
        g_rowtok[sidx] = t;
    }
}

// ---------------- packed f32x2 helpers --------------------------------------
typedef unsigned long long u64t;

__device__ __forceinline__ u64t pack2dup(float a) {
    u64t r;
    asm("mov.b64 %0, {%1, %1};" : "=l"(r) : "f"(a));
    return r;
}
__device__ __forceinline__ void fma2(u64t& acc, u64t a, u64t b) {
    asm("fma.rn.f32x2 %0, %1, %2, %0;" : "+l"(acc) : "l"(a), "l"(b));
}
__device__ __forceinline__ float2 unpack2(u64t v) {
    float2 r;
    asm("mov.b64 {%0, %1}, %2;" : "=f"(r.x), "=f"(r.y) : "l"(v));
    return r;
}

__device__ __forceinline__ float swiglu_f(float g, float u) {
    return (g / (1.0f + expf(-g))) * u;
}

// ---------------- generic 128x128x8 SGEMM -----------------------------------
// mode bit0: A = swiglu(A0, A1) elementwise   (A rows indexed directly)
// mode bit1: routed (M = g_cnt[z], seg = g_off[z], B += z*K*N)
// mode bit2: gather A rows via g_rowtok[seg+m]
__global__ void __launch_bounds__(256) sgemm128(
    const float* __restrict__ A0, const float* __restrict__ A1,
    const float* __restrict__ Bmat, float* __restrict__ C,
    int N, int K, int fixedM, int mode)
{
    const bool doSw   = (mode & 1) != 0;
    const bool routed = (mode & 2) != 0;
    const bool gather = (mode & 4) != 0;

    int e = blockIdx.z;
    int M, seg;
    const float* B = Bmat;
    if (routed) {
        M = g_cnt[e]; seg = g_off[e];
        B += (size_t)e * (size_t)K * (size_t)N;
    } else { M = fixedM; seg = 0; }

    int mbase = blockIdx.y * 128;
    if (mbase >= M) return;
    int nbase = blockIdx.x * 128;

    __shared__ float As[2][8][128];
    __shared__ float Bs[2][8][128];

    int tid  = threadIdx.x;
    int aRow = tid >> 1;            // 0..127
    int aK   = (tid & 1) * 4;       // 0 or 4
    int bK   = tid >> 5;            // 0..7
    int bN   = (tid & 31) * 4;      // 0..124

    int m = mbase + aRow;
    bool mv = (m < M);
    const float* aP0 = A0;
    const float* aP1 = A1;
    if (mv) {
        int r = seg + m;
        int src = gather ? g_rowtok[r] : r;
        aP0 = A0 + (size_t)src * K + aK;
        aP1 = A1 + (size_t)src * K + aK;
    }
    const float* bP = B + (size_t)bK * N + nbase + bN;

    float4 aF = make_float4(0.f, 0.f, 0.f, 0.f);
    float4 aG = make_float4(0.f, 0.f, 0.f, 0.f);
    float4 bF;

    if (mv) {
        aF = *(const float4*)(aP0);
        if (doSw) aG = *(const float4*)(aP1);
    }
    bF = *(const float4*)(bP);

    {
        float v0 = aF.x, v1 = aF.y, v2 = aF.z, v3 = aF.w;
        if (doSw) {
            v0 = swiglu_f(aF.x, aG.x); v1 = swiglu_f(aF.y, aG.y);
            v2 = swiglu_f(aF.z, aG.z); v3 = swiglu_f(aF.w, aG.w);
        }
        As[0][aK + 0][aRow] = v0; As[0][aK + 1][aRow] = v1;
        As[0][aK + 2][aRow] = v2; As[0][aK + 3][aRow] = v3;
        *(float4*)&Bs[0][bK][bN] = bF;
    }
    __syncthreads();

    u64t acc[8][4];
#pragma unroll
    for (int i = 0; i < 8; ++i)
#pragma unroll
        for (int j = 0; j < 4; ++j) acc[i][j] = 0ull;

    int row0 = (tid >> 4) * 8;
    int col0 = (tid & 15) * 8;

    int nk = K >> 3;
    int buf = 0;
    for (int kt = 0; kt < nk; ++kt) {
        bool more = (kt + 1) < nk;
        if (more) {
            if (mv) {
                aF = *(const float4*)(aP0 + (kt + 1) * 8);
                if (doSw) aG = *(const float4*)(aP1 + (kt + 1) * 8);
            }
            bF = *(const float4*)(bP + (size_t)(kt + 1) * 8 * N);
        }
#pragma unroll
        for (int kk = 0; kk < 8; ++kk) {
            float a[8];
            *(float4*)&a[0] = *(const float4*)&As[buf][kk][row0];
            *(float4*)&a[4] = *(const float4*)&As[buf][kk][row0 + 4];
            ulonglong2 blo = *(const ulonglong2*)&Bs[buf][kk][col0];
            ulonglong2 bhi = *(const ulonglong2*)&Bs[buf][kk][col0 + 4];
            u64t b2[4];
            b2[0] = blo.x; b2[1] = blo.y; b2[2] = bhi.x; b2[3] = bhi.y;
#pragma unroll
            for (int i = 0; i < 8; ++i) {
                u64t a2 = pack2dup(a[i]);
#pragma unroll
                for (int j = 0; j < 4; ++j) fma2(acc[i][j], a2, b2[j]);
            }
        }
        if (more) {
            int nb = buf ^ 1;
            float v0 = aF.x, v1 = aF.y, v2 = aF.z, v3 = aF.w;
            if (doSw) {
                v0 = swiglu_f(aF.x, aG.x); v1 = swiglu_f(aF.y, aG.y);
                v2 = swiglu_f(aF.z, aG.z); v3 = swiglu_f(aF.w, aG.w);
            }
            As[nb][aK + 0][aRow] = v0; As[nb][aK + 1][aRow] = v1;
            As[nb][aK + 2][aRow] = v2; As[nb][aK + 3][aRow] = v3;
            *(float4*)&Bs[nb][bK][bN] = bF;
        }
        __syncthreads();
        buf ^= 1;
    }

#pragma unroll
    for (int i = 0; i < 8; ++i) {
        int mm = mbase + row0 + i;
        if (mm < M) {
            float* cp = C + (size_t)(seg + mm) * N + nbase + col0;
            float2 p0 = unpack2(acc[i][0]);
            float2 p1 = unpack2(acc[i][1]);
            float2 p2 = unpack2(acc[i][2]);
            float2 p3 = unpack2(acc[i][3]);
            *(float4*)cp       = make_float4(p0.x, p0.y, p1.x, p1.y);
            *(float4*)(cp + 4) = make_float4(p2.x, p2.y, p3.x, p3.y);
        }
    }
}

// ---------------- combine: out += w0*Y[slot0] + w1*Y[slot1] ------------------
__global__ void combine_kernel(float* __restrict__ out) {
    int t = blockIdx.y;
    int c = (blockIdx.x * blockDim.x + threadIdx.x) * 4;
    int s0 = g_slot[2 * t + 0], s1 = g_slot[2 * t + 1];
    float w0 = g_wgt[2 * t + 0], w1 = g_wgt[2 * t + 1];
    const float4 y0 = *(const float4*)&g_Y[(size_t)s0 * H_DIM + c];
    const float4 y1 = *(const float4*)&g_Y[(size_t)s1 * H_DIM + c];
    float4 o = *(float4*)&out[(size_t)t * H_DIM + c];
    o.x += w0 * y0.x + w1 * y1.x;
    o.y += w0 * y0.y + w1 * y1.y;
    o.z += w0 * y0.z + w1 * y1.z;
    o.w += w0 * y0.w + w1 * y1.w;
    *(float4*)&out[(size_t)t * H_DIM + c] = o;
}

// ---------------- launch -----------------------------------------------------
extern "C" void kernel_launch(void* const* d_in, const int* in_sizes, int n_in,
                              void* d_out, int out_size) {
    (void)in_sizes; (void)n_in; (void)out_size;
    const float* x      = (const float*)d_in[0];
    // d_in[1] router_w, d_in[2] router_b: dead inputs (RandomSTE forward = noise)
    const float* w_gate = (const float*)d_in[3];
    const float* w_up   = (const float*)d_in[4];
    const float* w_down = (const float*)d_in[5];
    const float* sg     = (const float*)d_in[6];
    const float* su     = (const float*)d_in[7];
    const float* sd     = (const float*)d_in[8];
    float* out = (float*)d_out;

    void *pG = nullptr, *pU = nullptr, *pY = nullptr;
    cudaGetSymbolAddress(&pG, g_bufG);
    cudaGetSymbolAddress(&pU, g_bufU);
    cudaGetSymbolAddress(&pY, g_Y);
    float* bG = (float*)pG;
    float* bU = (float*)pU;
    float* Y  = (float*)pY;

    // routing
    zero_kernel<<<1, 32>>>();
    route_kernel<<<T_TOKENS / 256, 256>>>();
    scan_kernel<<<1, 1>>>();
    scatter_kernel<<<T_TOKENS / 256, 256>>>();

    // shared expert: Gs, Us = x @ sg, x @ su ; out = swiglu(Gs,Us) @ sd
    sgemm128<<<dim3(SI_DIM / 128, T_TOKENS / 128, 1), 256>>>(
        x, x, sg, bG, SI_DIM, H_DIM, T_TOKENS, 0);
    sgemm128<<<dim3(SI_DIM / 128, T_TOKENS / 128, 1), 256>>>(
        x, x, su, bU, SI_DIM, H_DIM, T_TOKENS, 0);
    sgemm128<<<dim3(H_DIM / 128, T_TOKENS / 128, 1), 256>>>(
        bG, bU, sd, out, H_DIM, SI_DIM, T_TOKENS, 1);

    // routed experts (grouped, gathered): G,U per slot; Y = swiglu(G,U) @ w_down[e]
    sgemm128<<<dim3(I_DIM / 128, T_TOKENS / 128, E_NUM), 256>>>(
        x, x, w_gate, bG, I_DIM, H_DIM, 0, 2 | 4);
    sgemm128<<<dim3(I_DIM / 128, T_TOKENS / 128, E_NUM), 256>>>(
        x, x, w_up, bU, I_DIM, H_DIM, 0, 2 | 4);
    sgemm128<<<dim3(H_DIM / 128, T_TOKENS / 128, E_NUM), 256>>>(
        bG, bU, w_down, Y, H_DIM, I_DIM, 0, 2 | 1);

    // combine routed contributions into out
    combine_kernel<<<dim3(H_DIM / 1024, T_TOKENS), 256>>>(out);
}

// round 5
// speedup vs baseline: 2.2171x; 2.2167x over previous
#include <cuda_runtime.h>
#include <cuda_bf16.h>
#include <cstdint>

#define T_TOKENS 4096
#define H_DIM    2048
#define I_DIM    1408
#define E_NUM    16
#define SI_DIM   2816
#define SLOTS    8192   // T * TOP_K

// ---------------- scratch (device globals; no runtime allocation) ----------
__device__ int   g_cnt[E_NUM];
__device__ int   g_off[E_NUM];
__device__ int   g_cur[E_NUM];
__device__ int   g_eid[T_TOKENS * 2];
__device__ float g_wgt[T_TOKENS * 2];
__device__ int   g_slot[T_TOKENS * 2];
__device__ int   g_rowtok[SLOTS];

// bf16 hi/lo split operands
__device__ __nv_bfloat16 g_xh[T_TOKENS * H_DIM];
__device__ __nv_bfloat16 g_xl[T_TOKENS * H_DIM];
__device__ __nv_bfloat16 g_wgh[E_NUM * I_DIM * H_DIM];   // w_gate^T  [E][I][H]
__device__ __nv_bfloat16 g_wgl[E_NUM * I_DIM * H_DIM];
__device__ __nv_bfloat16 g_wuh[E_NUM * I_DIM * H_DIM];   // w_up^T    [E][I][H]
__device__ __nv_bfloat16 g_wul[E_NUM * I_DIM * H_DIM];
__device__ __nv_bfloat16 g_wdh[E_NUM * H_DIM * I_DIM];   // w_down^T  [E][H][I]
__device__ __nv_bfloat16 g_wdl[E_NUM * H_DIM * I_DIM];
__device__ __nv_bfloat16 g_sgh[SI_DIM * H_DIM];          // sg^T [SI][H]
__device__ __nv_bfloat16 g_sgl[SI_DIM * H_DIM];
__device__ __nv_bfloat16 g_suh[SI_DIM * H_DIM];
__device__ __nv_bfloat16 g_sul[SI_DIM * H_DIM];
__device__ __nv_bfloat16 g_sdh[H_DIM * SI_DIM];          // sd^T [H][SI]
__device__ __nv_bfloat16 g_sdl[H_DIM * SI_DIM];
__device__ __nv_bfloat16 g_hrh[SLOTS * I_DIM];           // routed swiglu acts
__device__ __nv_bfloat16 g_hrl[SLOTS * I_DIM];
__device__ __nv_bfloat16 g_hsh[T_TOKENS * SI_DIM];       // shared swiglu acts
__device__ __nv_bfloat16 g_hsl[T_TOKENS * SI_DIM];
// time-shared fp32 scratch: shared G -> routed G -> routed Y (16.7M floats)
__device__ float g_Y[SLOTS * H_DIM];

// ---------------- threefry2x32 core (verified vs Random123 KAT) -------------
__device__ __forceinline__ uint32_t rotl32(uint32_t v, int r) {
    return (v << r) | (v >> (32 - r));
}

__device__ __forceinline__ void threefry2x32(uint32_t x0, uint32_t x1,
                                             uint32_t& o0, uint32_t& o1) {
    const uint32_t ks0 = 0u, ks1 = 42u, ks2 = 0u ^ 42u ^ 0x1BD11BDAu;
    x0 += ks0; x1 += ks1;
    x0 += x1; x1 = rotl32(x1, 13); x1 ^= x0;
    x0 += x1; x1 = rotl32(x1, 15); x1 ^= x0;
    x0 += x1; x1 = rotl32(x1, 26); x1 ^= x0;
    x0 += x1; x1 = rotl32(x1, 6);  x1 ^= x0;
    x0 += ks1; x1 += ks2 + 1u;
    x0 += x1; x1 = rotl32(x1, 17); x1 ^= x0;
    x0 += x1; x1 = rotl32(x1, 29); x1 ^= x0;
    x0 += x1; x1 = rotl32(x1, 16); x1 ^= x0;
    x0 += x1; x1 = rotl32(x1, 24); x1 ^= x0;
    x0 += ks2; x1 += ks0 + 2u;
    x0 += x1; x1 = rotl32(x1, 13); x1 ^= x0;
    x0 += x1; x1 = rotl32(x1, 15); x1 ^= x0;
    x0 += x1; x1 = rotl32(x1, 26); x1 ^= x0;
    x0 += x1; x1 = rotl32(x1, 6);  x1 ^= x0;
    x0 += ks0; x1 += ks1 + 3u;
    x0 += x1; x1 = rotl32(x1, 17); x1 ^= x0;
    x0 += x1; x1 = rotl32(x1, 29); x1 ^= x0;
    x0 += x1; x1 = rotl32(x1, 16); x1 ^= x0;
    x0 += x1; x1 = rotl32(x1, 24); x1 ^= x0;
    x0 += ks1; x1 += ks2 + 4u;
    x0 += x1; x1 = rotl32(x1, 13); x1 ^= x0;
    x0 += x1; x1 = rotl32(x1, 15); x1 ^= x0;
    x0 += x1; x1 = rotl32(x1, 26); x1 ^= x0;
    x0 += x1; x1 = rotl32(x1, 6);  x1 ^= x0;
    x0 += ks2; x1 += ks0 + 5u;
    o0 = x0; o1 = x1;
}

// XLA/CHLO erf_inv for f32 (Giles), w = -log1p(-x*x)
__device__ __forceinline__ float erfinv_xla(float x) {
    float w = -log1pf(-x * x);
    float p;
    if (w < 5.0f) {
        w -= 2.5f;
        p = 2.81022636e-08f;
        p = fmaf(p, w, 3.43273939e-07f);
        p = fmaf(p, w, -3.5233877e-06f);
        p = fmaf(p, w, -4.39150654e-06f);
        p = fmaf(p, w, 0.00021858087f);
        p = fmaf(p, w, -0.00125372503f);
        p = fmaf(p, w, -0.00417768164f);
        p = fmaf(p, w, 0.246640727f);
        p = fmaf(p, w, 1.50140941f);
    } else {
        w = sqrtf(w) - 3.0f;
        p = -0.000200214257f;
        p = fmaf(p, w, 0.000100950558f);
        p = fmaf(p, w, 0.00134934322f);
        p = fmaf(p, w, -0.00367342844f);
        p = fmaf(p, w, 0.00573950773f);
        p = fmaf(p, w, -0.0076224613f);
        p = fmaf(p, w, 0.00943887047f);
        p = fmaf(p, w, 1.00167406f);
        p = fmaf(p, w, 2.83297682f);
    }
    return p * x;
}

// ---------------- routing kernels ------------------------------------------
__global__ void zero_kernel() {
    if (threadIdx.x < E_NUM) g_cnt[threadIdx.x] = 0;
}

__global__ void route_kernel() {
    int t = blockIdx.x * blockDim.x + threadIdx.x;
    if (t >= T_TOKENS) return;
    float s[E_NUM];
#pragma unroll
    for (int e = 0; e < E_NUM; ++e) {
        uint32_t i = (uint32_t)t * E_NUM + (uint32_t)e;
        uint32_t o0, o1;
        threefry2x32(0u, i, o0, o1);
        uint32_t bits = o0 ^ o1;
        float u01 = __uint_as_float((bits >> 9) | 0x3f800000u) - 1.0f;
        float u = fmaf(u01, 2.0f, -0.99999994f);
        u = fmaxf(-0.99999994f, u);
        float nz = 1.4142135381698608f * erfinv_xla(u);
        s[e] = 1.0f / (1.0f + expf(-nz));
    }
    int b0 = 0;
#pragma unroll
    for (int e = 1; e < E_NUM; ++e) if (s[e] > s[b0]) b0 = e;
    int b1 = (b0 == 0) ? 1 : 0;
#pragma unroll
    for (int e = 0; e < E_NUM; ++e) if (e != b0 && s[e] > s[b1]) b1 = e;
    float sum = s[b0] + s[b1] + 1e-8f;
    g_eid[2 * t + 0] = b0;
    g_eid[2 * t + 1] = b1;
    g_wgt[2 * t + 0] = s[b0] / sum;
    g_wgt[2 * t + 1] = s[b1] / sum;
    atomicAdd(&g_cnt[b0], 1);
    atomicAdd(&g_cnt[b1], 1);
}

__global__ void scan_kernel() {
    int a = 0;
    for (int e = 0; e < E_NUM; ++e) { g_off[e] = a; g_cur[e] = a; a += g_cnt[e]; }
}

__global__ void scatter_kernel() {
    int t = blockIdx.x * blockDim.x + threadIdx.x;
    if (t >= T_TOKENS) return;
#pragma unroll
    for (int k = 0; k < 2; ++k) {
        int e = g_eid[2 * t + k];
        int sidx = atomicAdd(&g_cur[e], 1);
        g_slot[2 * t + k] = sidx;
        g_rowtok[sidx] = t;
    }
}

// ---------------- conversion kernels ----------------------------------------
__global__ void convert_x_kernel(const float* __restrict__ x,
                                 __nv_bfloat16* __restrict__ hi,
                                 __nv_bfloat16* __restrict__ lo) {
    int i = (blockIdx.x * blockDim.x + threadIdx.x) * 4;
    float4 v = *(const float4*)(x + i);
    __nv_bfloat16 h[4], l[4];
    float vv[4] = {v.x, v.y, v.z, v.w};
#pragma unroll
    for (int k = 0; k < 4; ++k) {
        h[k] = __float2bfloat16(vv[k]);
        l[k] = __float2bfloat16(vv[k] - __bfloat162float(h[k]));
    }
    *(uint2*)(hi + i) = *(uint2*)h;
    *(uint2*)(lo + i) = *(uint2*)l;
}

// transpose [R][C] fp32 -> [C][R] bf16 hi/lo (z = matrix index, offset z*R*C)
__global__ void transpose_conv(const float* __restrict__ src,
                               __nv_bfloat16* __restrict__ hi,
                               __nv_bfloat16* __restrict__ lo,
                               int R, int C) {
    __shared__ float tile[32][33];
    size_t zo = (size_t)blockIdx.z * (size_t)R * (size_t)C;
    int c0 = blockIdx.x * 32, r0 = blockIdx.y * 32;
#pragma unroll
    for (int j = threadIdx.y; j < 32; j += 8)
        tile[j][threadIdx.x] = src[zo + (size_t)(r0 + j) * C + c0 + threadIdx.x];
    __syncthreads();
#pragma unroll
    for (int jj = threadIdx.y; jj < 32; jj += 8) {
        int n = c0 + jj;
        int r = r0 + threadIdx.x;
        float v = tile[threadIdx.x][jj];
        __nv_bfloat16 h = __float2bfloat16(v);
        hi[zo + (size_t)n * R + r] = h;
        lo[zo + (size_t)n * R + r] = __float2bfloat16(v - __bfloat162float(h));
    }
}

// ---------------- warp-MMA helpers (portable PTX, no 'a'-suffix features) ---
__device__ __forceinline__ uint32_t smem_u32(const void* p) {
    uint32_t a;
    asm("{ .reg .u64 t; cvta.to.shared.u64 t, %1; cvt.u32.u64 %0, t; }"
        : "=r"(a) : "l"(p));
    return a;
}

__device__ __forceinline__ uint32_t swz(uint32_t off) {
    return off ^ ((off >> 3) & 0x70);
}

__device__ __forceinline__ void cp16(uint32_t s, const void* g) {
    asm volatile("cp.async.cg.shared.global [%0], [%1], 16;"
                 :: "r"(s), "l"(g) : "memory");
}
#define CP_COMMIT() asm volatile("cp.async.commit_group;" ::: "memory")
template <int N>
__device__ __forceinline__ void cp_wait() {
    asm volatile("cp.async.wait_group %0;" :: "n"(N) : "memory");
}

__device__ __forceinline__ void ldsm4(uint32_t& r0, uint32_t& r1,
                                      uint32_t& r2, uint32_t& r3, uint32_t a) {
    asm volatile("ldmatrix.sync.aligned.m8n8.x4.shared.b16 {%0,%1,%2,%3}, [%4];"
                 : "=r"(r0), "=r"(r1), "=r"(r2), "=r"(r3) : "r"(a));
}

__device__ __forceinline__ void mma16816(float* c, const uint32_t* a,
                                         uint32_t b0, uint32_t b1) {
    asm volatile(
        "mma.sync.aligned.m16n8k16.row.col.f32.bf16.bf16.f32 "
        "{%0,%1,%2,%3}, {%4,%5,%6,%7}, {%8,%9}, {%0,%1,%2,%3};"
        : "+f"(c[0]), "+f"(c[1]), "+f"(c[2]), "+f"(c[3])
        : "r"(a[0]), "r"(a[1]), "r"(a[2]), "r"(a[3]), "r"(b0), "r"(b1));
}

__device__ __forceinline__ float swiglu_f(float g, float u) {
    return (g / (1.0f + expf(-g))) * u;
}

// ---------------- split-bf16 warp-MMA GEMM -----------------------------------
// C[M,N] = A[M,K] @ B[N,K]^T, A/B bf16 (hi,lo), 3 passes (hh+hl+lh), fp32 acc.
// EPI 0: write fp32 to Cf.   EPI 1: u=acc, g=Gf[same idx]; write bf16 hi/lo
//                                   of swiglu(g,u) to Ohi/Olo.
// ROUTED: per-expert segment (M=g_cnt[z], rows offset g_off[z], B += z*N*K).
// GATHER: A row indices via g_rowtok.
// CTA 128x128, K-chunk 64, 8 warps (2x4), warp tile 64x32, 3-stage cp.async.
template <int EPI, bool ROUTED, bool GATHER>
__global__ void __launch_bounds__(256, 1)
mma_gemm(const __nv_bfloat16* __restrict__ Ahi, const __nv_bfloat16* __restrict__ Alo,
         const __nv_bfloat16* __restrict__ Bhi, const __nv_bfloat16* __restrict__ Blo,
         const float* __restrict__ Gf, float* __restrict__ Cf,
         __nv_bfloat16* __restrict__ Ohi, __nv_bfloat16* __restrict__ Olo,
         int K, int N, int fixedM)
{
    extern __shared__ char smem[];
    const int tid  = threadIdx.x;
    const int wid  = tid >> 5;
    const int lane = tid & 31;

    const int e = blockIdx.z;
    int M, seg;
    if (ROUTED) { M = g_cnt[e]; seg = g_off[e]; }
    else        { M = fixedM;   seg = 0; }
    const int mbase = blockIdx.y * 128;
    if (mbase >= M) return;
    const int nbase = blockIdx.x * 128;

    // SMEM: 3 stages x [Ah 16K | Al 16K | Bh 16K | Bl 16K]
    const uint32_t sb = smem_u32(smem);
    const uint32_t STAGE = 65536;

    // ---- cp.async geometry: row = tid>>1, 64B half = (tid&1)*64, 4x16B chunks
    const int lrow = tid >> 1;
    const int hb   = (tid & 1) * 64;
    uint32_t so[4];
#pragma unroll
    for (int j = 0; j < 4; ++j)
        so[j] = swz((uint32_t)lrow * 128u + (uint32_t)hb + (uint32_t)j * 16u);

    int arow;
    {
        bool v = (mbase + lrow) < M;
        if (ROUTED) {
            int slot = seg + mbase + lrow;
            if (GATHER) arow = v ? g_rowtok[slot] : 0;
            else        arow = v ? slot : seg;
        } else {
            arow = mbase + lrow;   // always valid (M multiple of 128)
        }
    }
    const size_t bexp = ROUTED ? (size_t)e * (size_t)N * (size_t)K : 0;
    const int brow = nbase + lrow;

    const char* gAh = (const char*)(Ahi + (size_t)arow * K) + hb;
    const char* gAl = (const char*)(Alo + (size_t)arow * K) + hb;
    const char* gBh = (const char*)(Bhi + bexp + (size_t)brow * K) + hb;
    const char* gBl = (const char*)(Blo + bexp + (size_t)brow * K) + hb;

    const int nk = K >> 6;

#define ISSUE_STAGE(slot, kt)                                                  \
    do {                                                                       \
        uint32_t b_ = sb + (uint32_t)(slot) * STAGE;                           \
        const char* a0_ = gAh + (size_t)(kt) * 128;                            \
        const char* a1_ = gAl + (size_t)(kt) * 128;                            \
        const char* b0_ = gBh + (size_t)(kt) * 128;                            \
        const char* b1_ = gBl + (size_t)(kt) * 128;                            \
        _Pragma("unroll")                                                      \
        for (int j_ = 0; j_ < 4; ++j_) cp16(b_ + so[j_],          a0_ + j_*16);\
        _Pragma("unroll")                                                      \
        for (int j_ = 0; j_ < 4; ++j_) cp16(b_ + 16384 + so[j_],  a1_ + j_*16);\
        _Pragma("unroll")                                                      \
        for (int j_ = 0; j_ < 4; ++j_) cp16(b_ + 32768 + so[j_],  b0_ + j_*16);\
        _Pragma("unroll")                                                      \
        for (int j_ = 0; j_ < 4; ++j_) cp16(b_ + 49152 + so[j_],  b1_ + j_*16);\
        CP_COMMIT();                                                           \
    } while (0)

    // ---- warp tiling: 2 (m) x 4 (n) warps; warp tile 64x32
    const int wm = (wid >> 2) * 64;
    const int wn = (wid & 3) * 32;

    // ldmatrix per-lane row offsets (byte offsets before swizzle)
    uint32_t aOff[4], bOff[2];
#pragma unroll
    for (int mf = 0; mf < 4; ++mf)
        aOff[mf] = (uint32_t)(wm + mf * 16 + (lane & 15)) * 128u
                 + (uint32_t)((lane >> 4) * 16);
#pragma unroll
    for (int nf2 = 0; nf2 < 2; ++nf2)
        bOff[nf2] = (uint32_t)(wn + nf2 * 16 + (lane & 7) + ((lane & 16) >> 1)) * 128u
                  + (uint32_t)(((lane >> 3) & 1) * 16);

    float acc[4][4][4];
#pragma unroll
    for (int i = 0; i < 4; ++i)
#pragma unroll
        for (int j = 0; j < 4; ++j)
#pragma unroll
            for (int q = 0; q < 4; ++q) acc[i][j][q] = 0.0f;

    // prologue
    ISSUE_STAGE(0, 0);
    if (nk > 1) ISSUE_STAGE(1, 1); else CP_COMMIT();

    for (int kt = 0; kt < nk; ++kt) {
        const int s = kt % 3;
        if (kt + 2 < nk) ISSUE_STAGE((kt + 2) % 3, kt + 2);
        if (kt + 2 < nk)      cp_wait<2>();
        else if (kt + 1 < nk) cp_wait<1>();
        else                  cp_wait<0>();
        __syncthreads();

        const uint32_t stb = sb + (uint32_t)s * STAGE;
#pragma unroll
        for (int ks = 0; ks < 4; ++ks) {
            uint32_t ah[4][4], al[4][4], bh[2][4], bl[2][4];
            const uint32_t kso = (uint32_t)ks * 32u;
#pragma unroll
            for (int mf = 0; mf < 4; ++mf) {
                uint32_t off = swz(aOff[mf] + kso);
                ldsm4(ah[mf][0], ah[mf][1], ah[mf][2], ah[mf][3], stb + off);
                ldsm4(al[mf][0], al[mf][1], al[mf][2], al[mf][3], stb + 16384 + off);
            }
#pragma unroll
            for (int nf2 = 0; nf2 < 2; ++nf2) {
                uint32_t off = swz(bOff[nf2] + kso);
                ldsm4(bh[nf2][0], bh[nf2][1], bh[nf2][2], bh[nf2][3], stb + 32768 + off);
                ldsm4(bl[nf2][0], bl[nf2][1], bl[nf2][2], bl[nf2][3], stb + 49152 + off);
            }
            // pass 1: hi*hi
#pragma unroll
            for (int mf = 0; mf < 4; ++mf)
#pragma unroll
                for (int nf = 0; nf < 4; ++nf)
                    mma16816(acc[mf][nf], ah[mf],
                             bh[nf >> 1][(nf & 1) * 2], bh[nf >> 1][(nf & 1) * 2 + 1]);
            // pass 2: hi*lo
#pragma unroll
            for (int mf = 0; mf < 4; ++mf)
#pragma unroll
                for (int nf = 0; nf < 4; ++nf)
                    mma16816(acc[mf][nf], ah[mf],
                             bl[nf >> 1][(nf & 1) * 2], bl[nf >> 1][(nf & 1) * 2 + 1]);
            // pass 3: lo*hi
#pragma unroll
            for (int mf = 0; mf < 4; ++mf)
#pragma unroll
                for (int nf = 0; nf < 4; ++nf)
                    mma16816(acc[mf][nf], al[mf],
                             bh[nf >> 1][(nf & 1) * 2], bh[nf >> 1][(nf & 1) * 2 + 1]);
        }
        __syncthreads();
    }
#undef ISSUE_STAGE

    // ---- epilogue
    const size_t rowoff = ROUTED ? (size_t)seg : 0;
#pragma unroll
    for (int mf = 0; mf < 4; ++mf) {
#pragma unroll
        for (int nf = 0; nf < 4; ++nf) {
            int r0 = mbase + wm + mf * 16 + (lane >> 2);
            int n0 = nbase + wn + nf * 8 + (lane & 3) * 2;
            float* c = acc[mf][nf];
            if (EPI == 0) {
                if (r0 < M)
                    *(float2*)&Cf[(rowoff + r0) * N + n0] = make_float2(c[0], c[1]);
                if (r0 + 8 < M)
                    *(float2*)&Cf[(rowoff + r0 + 8) * N + n0] = make_float2(c[2], c[3]);
            } else {
#pragma unroll
                for (int h = 0; h < 2; ++h) {
                    int r = r0 + h * 8;
                    if (r < M) {
                        size_t idx = (rowoff + r) * (size_t)N + n0;
                        float gg0 = Gf[idx], gg1 = Gf[idx + 1];
                        float a0 = swiglu_f(gg0, c[h * 2 + 0]);
                        float a1 = swiglu_f(gg1, c[h * 2 + 1]);
                        __nv_bfloat16 h0 = __float2bfloat16(a0);
                        __nv_bfloat16 h1 = __float2bfloat16(a1);
                        __nv_bfloat162 hp = __halves2bfloat162(h0, h1);
                        *(uint32_t*)&Ohi[idx] = *reinterpret_cast<uint32_t*>(&hp);
                        __nv_bfloat16 l0 = __float2bfloat16(a0 - __bfloat162float(h0));
                        __nv_bfloat16 l1 = __float2bfloat16(a1 - __bfloat162float(h1));
                        __nv_bfloat162 lp = __halves2bfloat162(l0, l1);
                        *(uint32_t*)&Olo[idx] = *reinterpret_cast<uint32_t*>(&lp);
                    }
                }
            }
        }
    }
}

// ---------------- combine: out += w0*Y[slot0] + w1*Y[slot1] ------------------
__global__ void combine_kernel(float* __restrict__ out) {
    int t = blockIdx.y;
    int c = (blockIdx.x * blockDim.x + threadIdx.x) * 4;
    int s0 = g_slot[2 * t + 0], s1 = g_slot[2 * t + 1];
    float w0 = g_wgt[2 * t + 0], w1 = g_wgt[2 * t + 1];
    const float4 y0 = *(const float4*)&g_Y[(size_t)s0 * H_DIM + c];
    const float4 y1 = *(const float4*)&g_Y[(size_t)s1 * H_DIM + c];
    float4 o = *(float4*)&out[(size_t)t * H_DIM + c];
    o.x += w0 * y0.x + w1 * y1.x;
    o.y += w0 * y0.y + w1 * y1.y;
    o.z += w0 * y0.z + w1 * y1.z;
    o.w += w0 * y0.w + w1 * y1.w;
    *(float4*)&out[(size_t)t * H_DIM + c] = o;
}

// ---------------- launch -----------------------------------------------------
extern "C" void kernel_launch(void* const* d_in, const int* in_sizes, int n_in,
                              void* d_out, int out_size) {
    (void)in_sizes; (void)n_in; (void)out_size;
    const float* x      = (const float*)d_in[0];
    // d_in[1] router_w, d_in[2] router_b: dead inputs (RandomSTE forward = noise)
    const float* w_gate = (const float*)d_in[3];
    const float* w_up   = (const float*)d_in[4];
    const float* w_down = (const float*)d_in[5];
    const float* sg     = (const float*)d_in[6];
    const float* su     = (const float*)d_in[7];
    const float* sd     = (const float*)d_in[8];
    float* out = (float*)d_out;

    auto sym = [](const void* s) {
        void* p = nullptr;
        cudaGetSymbolAddress(&p, s);
        return p;
    };
    __nv_bfloat16* xh  = (__nv_bfloat16*)sym(g_xh);
    __nv_bfloat16* xl  = (__nv_bfloat16*)sym(g_xl);
    __nv_bfloat16* wgh = (__nv_bfloat16*)sym(g_wgh);
    __nv_bfloat16* wgl = (__nv_bfloat16*)sym(g_wgl);
    __nv_bfloat16* wuh = (__nv_bfloat16*)sym(g_wuh);
    __nv_bfloat16* wul = (__nv_bfloat16*)sym(g_wul);
    __nv_bfloat16* wdh = (__nv_bfloat16*)sym(g_wdh);
    __nv_bfloat16* wdl = (__nv_bfloat16*)sym(g_wdl);
    __nv_bfloat16* sgh = (__nv_bfloat16*)sym(g_sgh);
    __nv_bfloat16* sgl = (__nv_bfloat16*)sym(g_sgl);
    __nv_bfloat16* suh = (__nv_bfloat16*)sym(g_suh);
    __nv_bfloat16* sul = (__nv_bfloat16*)sym(g_sul);
    __nv_bfloat16* sdh = (__nv_bfloat16*)sym(g_sdh);
    __nv_bfloat16* sdl = (__nv_bfloat16*)sym(g_sdl);
    __nv_bfloat16* hrh = (__nv_bfloat16*)sym(g_hrh);
    __nv_bfloat16* hrl = (__nv_bfloat16*)sym(g_hrl);
    __nv_bfloat16* hsh = (__nv_bfloat16*)sym(g_hsh);
    __nv_bfloat16* hsl = (__nv_bfloat16*)sym(g_hsl);
    float*         Yp  = (float*)sym(g_Y);

    const int SMEM = 3 * 65536;   // 196608
    cudaFuncSetAttribute(mma_gemm<0, false, false>,
                         cudaFuncAttributeMaxDynamicSharedMemorySize, SMEM);
    cudaFuncSetAttribute(mma_gemm<1, false, false>,
                         cudaFuncAttributeMaxDynamicSharedMemorySize, SMEM);
    cudaFuncSetAttribute(mma_gemm<0, true, true>,
                         cudaFuncAttributeMaxDynamicSharedMemorySize, SMEM);
    cudaFuncSetAttribute(mma_gemm<1, true, true>,
                         cudaFuncAttributeMaxDynamicSharedMemorySize, SMEM);
    cudaFuncSetAttribute(mma_gemm<0, true, false>,
                         cudaFuncAttributeMaxDynamicSharedMemorySize, SMEM);

    // routing
    zero_kernel<<<1, 32>>>();
    route_kernel<<<T_TOKENS / 256, 256>>>();
    scan_kernel<<<1, 1>>>();
    scatter_kernel<<<T_TOKENS / 256, 256>>>();

    // conversions
    convert_x_kernel<<<(T_TOKENS * H_DIM) / 1024, 256>>>(x, xh, xl);
    transpose_conv<<<dim3(I_DIM / 32, H_DIM / 32, E_NUM), dim3(32, 8)>>>(
        w_gate, wgh, wgl, H_DIM, I_DIM);
    transpose_conv<<<dim3(I_DIM / 32, H_DIM / 32, E_NUM), dim3(32, 8)>>>(
        w_up, wuh, wul, H_DIM, I_DIM);
    transpose_conv<<<dim3(H_DIM / 32, I_DIM / 32, E_NUM), dim3(32, 8)>>>(
        w_down, wdh, wdl, I_DIM, H_DIM);
    transpose_conv<<<dim3(SI_DIM / 32, H_DIM / 32, 1), dim3(32, 8)>>>(
        sg, sgh, sgl, H_DIM, SI_DIM);
    transpose_conv<<<dim3(SI_DIM / 32, H_DIM / 32, 1), dim3(32, 8)>>>(
        su, suh, sul, H_DIM, SI_DIM);
    transpose_conv<<<dim3(H_DIM / 32, SI_DIM / 32, 1), dim3(32, 8)>>>(
        sd, sdh, sdl, SI_DIM, H_DIM);

    // shared expert: gate -> G(g_Y), up(+swiglu) -> hs, down -> out
    mma_gemm<0, false, false>
        <<<dim3(SI_DIM / 128, T_TOKENS / 128, 1), 256, SMEM>>>(
            xh, xl, sgh, sgl, nullptr, Yp, nullptr, nullptr,
            H_DIM, SI_DIM, T_TOKENS);
    mma_gemm<1, false, false>
        <<<dim3(SI_DIM / 128, T_TOKENS / 128, 1), 256, SMEM>>>(
            xh, xl, suh, sul, Yp, nullptr, hsh, hsl,
            H_DIM, SI_DIM, T_TOKENS);

    // routed experts: gate -> G(g_Y), up(+swiglu) -> hr
    mma_gemm<0, true, true>
        <<<dim3(I_DIM / 128, SLOTS / 128, E_NUM), 256, SMEM>>>(
            xh, xl, wgh, wgl, nullptr, Yp, nullptr, nullptr,
            H_DIM, I_DIM, 0);
    mma_gemm<1, true, true>
        <<<dim3(I_DIM / 128, SLOTS / 128, E_NUM), 256, SMEM>>>(
            xh, xl, wuh, wul, Yp, nullptr, hrh, hrl,
            H_DIM, I_DIM, 0);

    // down projections: shared -> out (full overwrite), routed -> Y(g_Y)
    mma_gemm<0, false, false>
        <<<dim3(H_DIM / 128, T_TOKENS / 128, 1), 256, SMEM>>>(
            hsh, hsl, sdh, sdl, nullptr, out, nullptr, nullptr,
            SI_DIM, H_DIM, T_TOKENS);
    mma_gemm<0, true, false>
        <<<dim3(H_DIM / 128, SLOTS / 128, E_NUM), 256, SMEM>>>(
            hrh, hrl, wdh, wdl, nullptr, Yp, nullptr, nullptr,
            I_DIM, H_DIM, 0);

    // combine routed contributions into out
    combine_kernel<<<dim3(H_DIM / 1024, T_TOKENS), 256>>>(out);
}

// round 6
// speedup vs baseline: 2.4160x; 1.0897x over previous
#include <cuda_runtime.h>
#include <cuda_bf16.h>
#include <cstdint>

#define T_TOKENS 4096
#define H_DIM    2048
#define I_DIM    1408
#define E_NUM    16
#define SI_DIM   2816
#define SLOTS    8192   // T * TOP_K

// ---------------- scratch (device globals; no runtime allocation) ----------
__device__ int   g_cnt[E_NUM];
__device__ int   g_off[E_NUM];
__device__ int   g_cur[E_NUM];
__device__ int   g_eid[T_TOKENS * 2];
__device__ float g_wgt[T_TOKENS * 2];
__device__ int   g_slot[T_TOKENS * 2];
__device__ int   g_rowtok[SLOTS];

// bf16 hi/lo split operands
__device__ __nv_bfloat16 g_xh[T_TOKENS * H_DIM];
__device__ __nv_bfloat16 g_xl[T_TOKENS * H_DIM];
__device__ __nv_bfloat16 g_wgh[E_NUM * I_DIM * H_DIM];   // w_gate^T  [E][I][H]
__device__ __nv_bfloat16 g_wgl[E_NUM * I_DIM * H_DIM];
__device__ __nv_bfloat16 g_wuh[E_NUM * I_DIM * H_DIM];   // w_up^T    [E][I][H]
__device__ __nv_bfloat16 g_wul[E_NUM * I_DIM * H_DIM];
__device__ __nv_bfloat16 g_wdh[E_NUM * H_DIM * I_DIM];   // w_down^T  [E][H][I]
__device__ __nv_bfloat16 g_wdl[E_NUM * H_DIM * I_DIM];
__device__ __nv_bfloat16 g_sgh[SI_DIM * H_DIM];          // sg^T [SI][H]
__device__ __nv_bfloat16 g_sgl[SI_DIM * H_DIM];
__device__ __nv_bfloat16 g_suh[SI_DIM * H_DIM];
__device__ __nv_bfloat16 g_sul[SI_DIM * H_DIM];
__device__ __nv_bfloat16 g_sdh[H_DIM * SI_DIM];          // sd^T [H][SI]
__device__ __nv_bfloat16 g_sdl[H_DIM * SI_DIM];
__device__ __nv_bfloat16 g_hrh[SLOTS * I_DIM];           // routed swiglu acts
__device__ __nv_bfloat16 g_hrl[SLOTS * I_DIM];
__device__ __nv_bfloat16 g_hsh[T_TOKENS * SI_DIM];       // shared swiglu acts
__device__ __nv_bfloat16 g_hsl[T_TOKENS * SI_DIM];
__device__ float g_Y[SLOTS * H_DIM];                     // routed down output

// ---------------- threefry2x32 core (verified vs Random123 KAT) -------------
__device__ __forceinline__ uint32_t rotl32(uint32_t v, int r) {
    return (v << r) | (v >> (32 - r));
}

__device__ __forceinline__ void threefry2x32(uint32_t x0, uint32_t x1,
                                             uint32_t& o0, uint32_t& o1) {
    const uint32_t ks0 = 0u, ks1 = 42u, ks2 = 0u ^ 42u ^ 0x1BD11BDAu;
    x0 += ks0; x1 += ks1;
    x0 += x1; x1 = rotl32(x1, 13); x1 ^= x0;
    x0 += x1; x1 = rotl32(x1, 15); x1 ^= x0;
    x0 += x1; x1 = rotl32(x1, 26); x1 ^= x0;
    x0 += x1; x1 = rotl32(x1, 6);  x1 ^= x0;
    x0 += ks1; x1 += ks2 + 1u;
    x0 += x1; x1 = rotl32(x1, 17); x1 ^= x0;
    x0 += x1; x1 = rotl32(x1, 29); x1 ^= x0;
    x0 += x1; x1 = rotl32(x1, 16); x1 ^= x0;
    x0 += x1; x1 = rotl32(x1, 24); x1 ^= x0;
    x0 += ks2; x1 += ks0 + 2u;
    x0 += x1; x1 = rotl32(x1, 13); x1 ^= x0;
    x0 += x1; x1 = rotl32(x1, 15); x1 ^= x0;
    x0 += x1; x1 = rotl32(x1, 26); x1 ^= x0;
    x0 += x1; x1 = rotl32(x1, 6);  x1 ^= x0;
    x0 += ks0; x1 += ks1 + 3u;
    x0 += x1; x1 = rotl32(x1, 17); x1 ^= x0;
    x0 += x1; x1 = rotl32(x1, 29); x1 ^= x0;
    x0 += x1; x1 = rotl32(x1, 16); x1 ^= x0;
    x0 += x1; x1 = rotl32(x1, 24); x1 ^= x0;
    x0 += ks1; x1 += ks2 + 4u;
    x0 += x1; x1 = rotl32(x1, 13); x1 ^= x0;
    x0 += x1; x1 = rotl32(x1, 15); x1 ^= x0;
    x0 += x1; x1 = rotl32(x1, 26); x1 ^= x0;
    x0 += x1; x1 = rotl32(x1, 6);  x1 ^= x0;
    x0 += ks2; x1 += ks0 + 5u;
    o0 = x0; o1 = x1;
}

// XLA/CHLO erf_inv for f32 (Giles), w = -log1p(-x*x)
__device__ __forceinline__ float erfinv_xla(float x) {
    float w = -log1pf(-x * x);
    float p;
    if (w < 5.0f) {
        w -= 2.5f;
        p = 2.81022636e-08f;
        p = fmaf(p, w, 3.43273939e-07f);
        p = fmaf(p, w, -3.5233877e-06f);
        p = fmaf(p, w, -4.39150654e-06f);
        p = fmaf(p, w, 0.00021858087f);
        p = fmaf(p, w, -0.00125372503f);
        p = fmaf(p, w, -0.00417768164f);
        p = fmaf(p, w, 0.246640727f);
        p = fmaf(p, w, 1.50140941f);
    } else {
        w = sqrtf(w) - 3.0f;
        p = -0.000200214257f;
        p = fmaf(p, w, 0.000100950558f);
        p = fmaf(p, w, 0.00134934322f);
        p = fmaf(p, w, -0.00367342844f);
        p = fmaf(p, w, 0.00573950773f);
        p = fmaf(p, w, -0.0076224613f);
        p = fmaf(p, w, 0.00943887047f);
        p = fmaf(p, w, 1.00167406f);
        p = fmaf(p, w, 2.83297682f);
    }
    return p * x;
}

// ---------------- routing kernels ------------------------------------------
__global__ void zero_kernel() {
    if (threadIdx.x < E_NUM) g_cnt[threadIdx.x] = 0;
}

__global__ void route_kernel() {
    int t = blockIdx.x * blockDim.x + threadIdx.x;
    if (t >= T_TOKENS) return;
    float s[E_NUM];
#pragma unroll
    for (int e = 0; e < E_NUM; ++e) {
        uint32_t i = (uint32_t)t * E_NUM + (uint32_t)e;
        uint32_t o0, o1;
        threefry2x32(0u, i, o0, o1);
        uint32_t bits = o0 ^ o1;
        float u01 = __uint_as_float((bits >> 9) | 0x3f800000u) - 1.0f;
        float u = fmaf(u01, 2.0f, -0.99999994f);
        u = fmaxf(-0.99999994f, u);
        float nz = 1.4142135381698608f * erfinv_xla(u);
        s[e] = 1.0f / (1.0f + expf(-nz));
    }
    int b0 = 0;
#pragma unroll
    for (int e = 1; e < E_NUM; ++e) if (s[e] > s[b0]) b0 = e;
    int b1 = (b0 == 0) ? 1 : 0;
#pragma unroll
    for (int e = 0; e < E_NUM; ++e) if (e != b0 && s[e] > s[b1]) b1 = e;
    float sum = s[b0] + s[b1] + 1e-8f;
    g_eid[2 * t + 0] = b0;
    g_eid[2 * t + 1] = b1;
    g_wgt[2 * t + 0] = s[b0] / sum;
    g_wgt[2 * t + 1] = s[b1] / sum;
    atomicAdd(&g_cnt[b0], 1);
    atomicAdd(&g_cnt[b1], 1);
}

__global__ void scan_kernel() {
    int a = 0;
    for (int e = 0; e < E_NUM; ++e) { g_off[e] = a; g_cur[e] = a; a += g_cnt[e]; }
}

__global__ void scatter_kernel() {
    int t = blockIdx.x * blockDim.x + threadIdx.x;
    if (t >= T_TOKENS) return;
#pragma unroll
    for (int k = 0; k < 2; ++k) {
        int e = g_eid[2 * t + k];
        int sidx = atomicAdd(&g_cur[e], 1);
        g_slot[2 * t + k] = sidx;
        g_rowtok[sidx] = t;
    }
}

// ---------------- conversion kernels ----------------------------------------
__global__ void convert_x_kernel(const float* __restrict__ x,
                                 __nv_bfloat16* __restrict__ hi,
                                 __nv_bfloat16* __restrict__ lo) {
    int i = (blockIdx.x * blockDim.x + threadIdx.x) * 4;
    float4 v = *(const float4*)(x + i);
    __nv_bfloat16 h[4], l[4];
    float vv[4] = {v.x, v.y, v.z, v.w};
#pragma unroll
    for (int k = 0; k < 4; ++k) {
        h[k] = __float2bfloat16(vv[k]);
        l[k] = __float2bfloat16(vv[k] - __bfloat162float(h[k]));
    }
    *(uint2*)(hi + i) = *(uint2*)h;
    *(uint2*)(lo + i) = *(uint2*)l;
}

// transpose [R][C] fp32 -> [C][R] bf16 hi/lo (z = matrix index, offset z*R*C)
__global__ void transpose_conv(const float* __restrict__ src,
                               __nv_bfloat16* __restrict__ hi,
                               __nv_bfloat16* __restrict__ lo,
                               int R, int C) {
    __shared__ float tile[32][33];
    size_t zo = (size_t)blockIdx.z * (size_t)R * (size_t)C;
    int c0 = blockIdx.x * 32, r0 = blockIdx.y * 32;
#pragma unroll
    for (int j = threadIdx.y; j < 32; j += 8)
        tile[j][threadIdx.x] = src[zo + (size_t)(r0 + j) * C + c0 + threadIdx.x];
    __syncthreads();
#pragma unroll
    for (int jj = threadIdx.y; jj < 32; jj += 8) {
        int n = c0 + jj;
        int r = r0 + threadIdx.x;
        float v = tile[threadIdx.x][jj];
        __nv_bfloat16 h = __float2bfloat16(v);
        hi[zo + (size_t)n * R + r] = h;
        lo[zo + (size_t)n * R + r] = __float2bfloat16(v - __bfloat162float(h));
    }
}

// ---------------- warp-MMA helpers (portable PTX) ----------------------------
__device__ __forceinline__ uint32_t smem_u32(const void* p) {
    uint32_t a;
    asm("{ .reg .u64 t; cvta.to.shared.u64 t, %1; cvt.u32.u64 %0, t; }"
        : "=r"(a) : "l"(p));
    return a;
}

__device__ __forceinline__ uint32_t swz128(uint32_t off) {
    return off ^ ((off >> 3) & 0x70);
}
__device__ __forceinline__ uint32_t swz64(uint32_t off) {
    return off ^ ((off >> 3) & 0x30);
}

__device__ __forceinline__ void cp16(uint32_t s, const void* g) {
    asm volatile("cp.async.cg.shared.global [%0], [%1], 16;"
                 :: "r"(s), "l"(g) : "memory");
}
#define CP_COMMIT() asm volatile("cp.async.commit_group;" ::: "memory")
template <int N>
__device__ __forceinline__ void cp_wait() {
    asm volatile("cp.async.wait_group %0;" :: "n"(N) : "memory");
}

__device__ __forceinline__ void ldsm4(uint32_t* r, uint32_t a) {
    asm volatile("ldmatrix.sync.aligned.m8n8.x4.shared.b16 {%0,%1,%2,%3}, [%4];"
                 : "=r"(r[0]), "=r"(r[1]), "=r"(r[2]), "=r"(r[3]) : "r"(a));
}

__device__ __forceinline__ void mma16816(float* c, const uint32_t* a,
                                         uint32_t b0, uint32_t b1) {
    asm volatile(
        "mma.sync.aligned.m16n8k16.row.col.f32.bf16.bf16.f32 "
        "{%0,%1,%2,%3}, {%4,%5,%6,%7}, {%8,%9}, {%0,%1,%2,%3};"
        : "+f"(c[0]), "+f"(c[1]), "+f"(c[2]), "+f"(c[3])
        : "r"(a[0]), "r"(a[1]), "r"(a[2]), "r"(a[3]), "r"(b0), "r"(b1));
}

__device__ __forceinline__ float swiglu_f(float g, float u) {
    return (g / (1.0f + expf(-g))) * u;
}

// =============================================================================
// FUSED gate+up GEMM: G = A@B1^T, U = A@B2^T (split-bf16, 3 passes each),
// epilogue writes bf16 hi/lo of swiglu(G,U).
// CTA 128x128, K-chunk 32 (64B rows, SW64), 3 stages, 8 warps (2x4), wt 64x32.
// =============================================================================
#define STAGE_F 49152
template <bool ROUTED, bool GATHER>
__global__ void __launch_bounds__(256, 1)
mma_fused(const __nv_bfloat16* __restrict__ Ahi, const __nv_bfloat16* __restrict__ Alo,
          const __nv_bfloat16* __restrict__ B1hi, const __nv_bfloat16* __restrict__ B1lo,
          const __nv_bfloat16* __restrict__ B2hi, const __nv_bfloat16* __restrict__ B2lo,
          __nv_bfloat16* __restrict__ Ohi, __nv_bfloat16* __restrict__ Olo,
          int K, int N, int fixedM)
{
    extern __shared__ char smem[];
    const int tid  = threadIdx.x;
    const int wid  = tid >> 5;
    const int lane = tid & 31;

    const int e = blockIdx.z;
    int M, seg;
    if (ROUTED) { M = g_cnt[e]; seg = g_off[e]; }
    else        { M = fixedM;   seg = 0; }
    const int mbase = blockIdx.y * 128;
    if (mbase >= M) return;
    const int nbase = blockIdx.x * 128;

    const uint32_t sb = smem_u32(smem);

    // cp.async geometry: row = tid>>1 (0..127), 32B half = (tid&1)*32, 2x16B
    const int lrow = tid >> 1;
    const int hb   = (tid & 1) * 32;
    uint32_t so[2];
#pragma unroll
    for (int j = 0; j < 2; ++j)
        so[j] = swz64((uint32_t)lrow * 64u + (uint32_t)hb + (uint32_t)j * 16u);

    int arow;
    {
        bool v = (mbase + lrow) < M;
        if (ROUTED) {
            int slot = seg + mbase + lrow;
            if (GATHER) arow = v ? g_rowtok[slot] : 0;
            else        arow = v ? slot : seg;
        } else {
            arow = mbase + lrow;
        }
    }
    const size_t bexp = ROUTED ? (size_t)e * (size_t)N * (size_t)K : 0;
    const int brow = nbase + lrow;

    const char* gA0 = (const char*)(Ahi + (size_t)arow * K) + hb;
    const char* gA1 = (const char*)(Alo + (size_t)arow * K) + hb;
    const char* gB1h = (const char*)(B1hi + bexp + (size_t)brow * K) + hb;
    const char* gB1l = (const char*)(B1lo + bexp + (size_t)brow * K) + hb;
    const char* gB2h = (const char*)(B2hi + bexp + (size_t)brow * K) + hb;
    const char* gB2l = (const char*)(B2lo + bexp + (size_t)brow * K) + hb;

    const int nk = K >> 5;   // K-chunk 32

#define ISSUE_F(slot, kt)                                                      \
    do {                                                                       \
        uint32_t b_ = sb + (uint32_t)(slot) * STAGE_F;                         \
        size_t ko_ = (size_t)(kt) * 64;                                        \
        _Pragma("unroll")                                                      \
        for (int j_ = 0; j_ < 2; ++j_) {                                       \
            cp16(b_ +         so[j_], gA0  + ko_ + j_ * 16);                   \
            cp16(b_ +  8192 + so[j_], gA1  + ko_ + j_ * 16);                   \
            cp16(b_ + 16384 + so[j_], gB1h + ko_ + j_ * 16);                   \
            cp16(b_ + 24576 + so[j_], gB1l + ko_ + j_ * 16);                   \
            cp16(b_ + 32768 + so[j_], gB2h + ko_ + j_ * 16);                   \
            cp16(b_ + 40960 + so[j_], gB2l + ko_ + j_ * 16);                   \
        }                                                                      \
        CP_COMMIT();                                                           \
    } while (0)

    // warp tiling: 2 (m) x 4 (n) warps, warp tile 64x32
    const int wm = (wid >> 2) * 64;
    const int wn = (wid & 3) * 32;

    uint32_t aOff[4], bOff[2];
#pragma unroll
    for (int mf = 0; mf < 4; ++mf)
        aOff[mf] = (uint32_t)(wm + mf * 16 + (lane & 15)) * 64u
                 + (uint32_t)((lane >> 4) * 16);
#pragma unroll
    for (int nf2 = 0; nf2 < 2; ++nf2)
        bOff[nf2] = (uint32_t)(wn + nf2 * 16 + (lane & 7) + ((lane & 16) >> 1)) * 64u
                  + (uint32_t)(((lane >> 3) & 1) * 16);

    float accG[4][4][4], accU[4][4][4];
#pragma unroll
    for (int i = 0; i < 4; ++i)
#pragma unroll
        for (int j = 0; j < 4; ++j)
#pragma unroll
            for (int q = 0; q < 4; ++q) { accG[i][j][q] = 0.0f; accU[i][j][q] = 0.0f; }

    ISSUE_F(0, 0);
    ISSUE_F(1, 1);

    for (int kt = 0; kt < nk; ++kt) {
        const int s = kt % 3;
        if (kt + 1 < nk) cp_wait<1>(); else cp_wait<0>();
        __syncthreads();
        if (kt + 2 < nk) ISSUE_F((kt + 2) % 3, kt + 2);

        const uint32_t stb = sb + (uint32_t)s * STAGE_F;
#pragma unroll
        for (int ks = 0; ks < 2; ++ks) {
            const uint32_t kso = (uint32_t)ks * 32u;
            uint32_t ah[4][4], al[4][4], bh[2][4], bl[2][4];
#pragma unroll
            for (int mf = 0; mf < 4; ++mf) {
                uint32_t off = swz64(aOff[mf] + kso);
                ldsm4(ah[mf], stb + off);
                ldsm4(al[mf], stb + 8192 + off);
            }
            // ---- matrix 1 (gate) ----
#pragma unroll
            for (int nf2 = 0; nf2 < 2; ++nf2) {
                uint32_t off = swz64(bOff[nf2] + kso);
                ldsm4(bh[nf2], stb + 16384 + off);
                ldsm4(bl[nf2], stb + 24576 + off);
            }
#pragma unroll
            for (int mf = 0; mf < 4; ++mf)
#pragma unroll
                for (int nf = 0; nf < 4; ++nf)
                    mma16816(accG[mf][nf], ah[mf],
                             bh[nf >> 1][(nf & 1) * 2], bh[nf >> 1][(nf & 1) * 2 + 1]);
#pragma unroll
            for (int mf = 0; mf < 4; ++mf)
#pragma unroll
                for (int nf = 0; nf < 4; ++nf)
                    mma16816(accG[mf][nf], al[mf],
                             bh[nf >> 1][(nf & 1) * 2], bh[nf >> 1][(nf & 1) * 2 + 1]);
#pragma unroll
            for (int mf = 0; mf < 4; ++mf)
#pragma unroll
                for (int nf = 0; nf < 4; ++nf)
                    mma16816(accG[mf][nf], ah[mf],
                             bl[nf >> 1][(nf & 1) * 2], bl[nf >> 1][(nf & 1) * 2 + 1]);
            // ---- matrix 2 (up) ----
#pragma unroll
            for (int nf2 = 0; nf2 < 2; ++nf2) {
                uint32_t off = swz64(bOff[nf2] + kso);
                ldsm4(bh[nf2], stb + 32768 + off);
                ldsm4(bl[nf2], stb + 40960 + off);
            }
#pragma unroll
            for (int mf = 0; mf < 4; ++mf)
#pragma unroll
                for (int nf = 0; nf < 4; ++nf)
                    mma16816(accU[mf][nf], ah[mf],
                             bh[nf >> 1][(nf & 1) * 2], bh[nf >> 1][(nf & 1) * 2 + 1]);
#pragma unroll
            for (int mf = 0; mf < 4; ++mf)
#pragma unroll
                for (int nf = 0; nf < 4; ++nf)
                    mma16816(accU[mf][nf], al[mf],
                             bh[nf >> 1][(nf & 1) * 2], bh[nf >> 1][(nf & 1) * 2 + 1]);
#pragma unroll
            for (int mf = 0; mf < 4; ++mf)
#pragma unroll
                for (int nf = 0; nf < 4; ++nf)
                    mma16816(accU[mf][nf], ah[mf],
                             bl[nf >> 1][(nf & 1) * 2], bl[nf >> 1][(nf & 1) * 2 + 1]);
        }
    }
#undef ISSUE_F

    // epilogue: swiglu -> bf16 hi/lo
    const size_t rowoff = ROUTED ? (size_t)seg : 0;
#pragma unroll
    for (int mf = 0; mf < 4; ++mf) {
#pragma unroll
        for (int nf = 0; nf < 4; ++nf) {
            int r0 = mbase + wm + mf * 16 + (lane >> 2);
            int n0 = nbase + wn + nf * 8 + (lane & 3) * 2;
            float* cg = accG[mf][nf];
            float* cu = accU[mf][nf];
#pragma unroll
            for (int h = 0; h < 2; ++h) {
                int r = r0 + h * 8;
                if (r < M) {
                    size_t idx = (rowoff + r) * (size_t)N + n0;
                    float a0 = swiglu_f(cg[h * 2 + 0], cu[h * 2 + 0]);
                    float a1 = swiglu_f(cg[h * 2 + 1], cu[h * 2 + 1]);
                    __nv_bfloat16 h0 = __float2bfloat16(a0);
                    __nv_bfloat16 h1 = __float2bfloat16(a1);
                    __nv_bfloat162 hp = __halves2bfloat162(h0, h1);
                    *(uint32_t*)&Ohi[idx] = *reinterpret_cast<uint32_t*>(&hp);
                    __nv_bfloat16 l0 = __float2bfloat16(a0 - __bfloat162float(h0));
                    __nv_bfloat16 l1 = __float2bfloat16(a1 - __bfloat162float(h1));
                    __nv_bfloat162 lp = __halves2bfloat162(l0, l1);
                    *(uint32_t*)&Olo[idx] = *reinterpret_cast<uint32_t*>(&lp);
                }
            }
        }
    }
}

// =============================================================================
// DOWN GEMM: C = A@B^T fp32 out. CTA 128x128, K-chunk 64 (SW128), 3 stages.
// =============================================================================
#define STAGE_D 65536
template <bool ROUTED>
__global__ void __launch_bounds__(256, 1)
mma_down(const __nv_bfloat16* __restrict__ Ahi, const __nv_bfloat16* __restrict__ Alo,
         const __nv_bfloat16* __restrict__ Bhi, const __nv_bfloat16* __restrict__ Blo,
         float* __restrict__ Cf, int K, int N, int fixedM)
{
    extern __shared__ char smem[];
    const int tid  = threadIdx.x;
    const int wid  = tid >> 5;
    const int lane = tid & 31;

    const int e = blockIdx.z;
    int M, seg;
    if (ROUTED) { M = g_cnt[e]; seg = g_off[e]; }
    else        { M = fixedM;   seg = 0; }
    const int mbase = blockIdx.y * 128;
    if (mbase >= M) return;
    const int nbase = blockIdx.x * 128;

    const uint32_t sb = smem_u32(smem);

    const int lrow = tid >> 1;
    const int hb   = (tid & 1) * 64;
    uint32_t so[4];
#pragma unroll
    for (int j = 0; j < 4; ++j)
        so[j] = swz128((uint32_t)lrow * 128u + (uint32_t)hb + (uint32_t)j * 16u);

    int arow;
    {
        bool v = (mbase + lrow) < M;
        if (ROUTED) arow = v ? (seg + mbase + lrow) : seg;
        else        arow = mbase + lrow;
    }
    const size_t bexp = ROUTED ? (size_t)e * (size_t)N * (size_t)K : 0;
    const int brow = nbase + lrow;

    const char* gAh = (const char*)(Ahi + (size_t)arow * K) + hb;
    const char* gAl = (const char*)(Alo + (size_t)arow * K) + hb;
    const char* gBh = (const char*)(Bhi + bexp + (size_t)brow * K) + hb;
    const char* gBl = (const char*)(Blo + bexp + (size_t)brow * K) + hb;

    const int nk = K >> 6;

#define ISSUE_D(slot, kt)                                                      \
    do {                                                                       \
        uint32_t b_ = sb + (uint32_t)(slot) * STAGE_D;                         \
        size_t ko_ = (size_t)(kt) * 128;                                       \
        _Pragma("unroll")                                                      \
        for (int j_ = 0; j_ < 4; ++j_) {                                       \
            cp16(b_ +         so[j_], gAh + ko_ + j_ * 16);                    \
            cp16(b_ + 16384 + so[j_], gAl + ko_ + j_ * 16);                    \
            cp16(b_ + 32768 + so[j_], gBh + ko_ + j_ * 16);                    \
            cp16(b_ + 49152 + so[j_], gBl + ko_ + j_ * 16);                    \
        }                                                                      \
        CP_COMMIT();                                                           \
    } while (0)

    const int wm = (wid >> 2) * 64;
    const int wn = (wid & 3) * 32;

    uint32_t aOff[4], bOff[2];
#pragma unroll
    for (int mf = 0; mf < 4; ++mf)
        aOff[mf] = (uint32_t)(wm + mf * 16 + (lane & 15)) * 128u
                 + (uint32_t)((lane >> 4) * 16);
#pragma unroll
    for (int nf2 = 0; nf2 < 2; ++nf2)
        bOff[nf2] = (uint32_t)(wn + nf2 * 16 + (lane & 7) + ((lane & 16) >> 1)) * 128u
                  + (uint32_t)(((lane >> 3) & 1) * 16);

    float acc[4][4][4];
#pragma unroll
    for (int i = 0; i < 4; ++i)
#pragma unroll
        for (int j = 0; j < 4; ++j)
#pragma unroll
            for (int q = 0; q < 4; ++q) acc[i][j][q] = 0.0f;

    ISSUE_D(0, 0);
    ISSUE_D(1, 1);

    for (int kt = 0; kt < nk; ++kt) {
        const int s = kt % 3;
        if (kt + 1 < nk) cp_wait<1>(); else cp_wait<0>();
        __syncthreads();
        if (kt + 2 < nk) ISSUE_D((kt + 2) % 3, kt + 2);

        const uint32_t stb = sb + (uint32_t)s * STAGE_D;
#pragma unroll
        for (int ks = 0; ks < 4; ++ks) {
            const uint32_t kso = (uint32_t)ks * 32u;
            uint32_t ah[4][4], al[4][4], bh[2][4], bl[2][4];
#pragma unroll
            for (int mf = 0; mf < 4; ++mf) {
                uint32_t off = swz128(aOff[mf] + kso);
                ldsm4(ah[mf], stb + off);
                ldsm4(al[mf], stb + 16384 + off);
            }
#pragma unroll
            for (int nf2 = 0; nf2 < 2; ++nf2) {
                uint32_t off = swz128(bOff[nf2] + kso);
                ldsm4(bh[nf2], stb + 32768 + off);
                ldsm4(bl[nf2], stb + 49152 + off);
            }
#pragma unroll
            for (int mf = 0; mf < 4; ++mf)
#pragma unroll
                for (int nf = 0; nf < 4; ++nf)
                    mma16816(acc[mf][nf], ah[mf],
                             bh[nf >> 1][(nf & 1) * 2], bh[nf >> 1][(nf & 1) * 2 + 1]);
#pragma unroll
            for (int mf = 0; mf < 4; ++mf)
#pragma unroll
                for (int nf = 0; nf < 4; ++nf)
                    mma16816(acc[mf][nf], al[mf],
                             bh[nf >> 1][(nf & 1) * 2], bh[nf >> 1][(nf & 1) * 2 + 1]);
#pragma unroll
            for (int mf = 0; mf < 4; ++mf)
#pragma unroll
                for (int nf = 0; nf < 4; ++nf)
                    mma16816(acc[mf][nf], ah[mf],
                             bl[nf >> 1][(nf & 1) * 2], bl[nf >> 1][(nf & 1) * 2 + 1]);
        }
    }
#undef ISSUE_D

    const size_t rowoff = ROUTED ? (size_t)seg : 0;
#pragma unroll
    for (int mf = 0; mf < 4; ++mf) {
#pragma unroll
        for (int nf = 0; nf < 4; ++nf) {
            int r0 = mbase + wm + mf * 16 + (lane >> 2);
            int n0 = nbase + wn + nf * 8 + (lane & 3) * 2;
            float* c = acc[mf][nf];
            if (r0 < M)
                *(float2*)&Cf[(rowoff + r0) * (size_t)N + n0] = make_float2(c[0], c[1]);
            if (r0 + 8 < M)
                *(float2*)&Cf[(rowoff + r0 + 8) * (size_t)N + n0] = make_float2(c[2], c[3]);
        }
    }
}

// ---------------- combine: out += w0*Y[slot0] + w1*Y[slot1] ------------------
__global__ void combine_kernel(float* __restrict__ out) {
    int t = blockIdx.y;
    int c = (blockIdx.x * blockDim.x + threadIdx.x) * 4;
    int s0 = g_slot[2 * t + 0], s1 = g_slot[2 * t + 1];
    float w0 = g_wgt[2 * t + 0], w1 = g_wgt[2 * t + 1];
    const float4 y0 = *(const float4*)&g_Y[(size_t)s0 * H_DIM + c];
    const float4 y1 = *(const float4*)&g_Y[(size_t)s1 * H_DIM + c];
    float4 o = *(float4*)&out[(size_t)t * H_DIM + c];
    o.x += w0 * y0.x + w1 * y1.x;
    o.y += w0 * y0.y + w1 * y1.y;
    o.z += w0 * y0.z + w1 * y1.z;
    o.w += w0 * y0.w + w1 * y1.w;
    *(float4*)&out[(size_t)t * H_DIM + c] = o;
}

// ---------------- launch -----------------------------------------------------
extern "C" void kernel_launch(void* const* d_in, const int* in_sizes, int n_in,
                              void* d_out, int out_size) {
    (void)in_sizes; (void)n_in; (void)out_size;
    const float* x      = (const float*)d_in[0];
    // d_in[1] router_w, d_in[2] router_b: dead inputs (RandomSTE forward = noise)
    const float* w_gate = (const float*)d_in[3];
    const float* w_up   = (const float*)d_in[4];
    const float* w_down = (const float*)d_in[5];
    const float* sg     = (const float*)d_in[6];
    const float* su     = (const float*)d_in[7];
    const float* sd     = (const float*)d_in[8];
    float* out = (float*)d_out;

    auto sym = [](const void* s) {
        void* p = nullptr;
        cudaGetSymbolAddress(&p, s);
        return p;
    };
    __nv_bfloat16* xh  = (__nv_bfloat16*)sym(g_xh);
    __nv_bfloat16* xl  = (__nv_bfloat16*)sym(g_xl);
    __nv_bfloat16* wgh = (__nv_bfloat16*)sym(g_wgh);
    __nv_bfloat16* wgl = (__nv_bfloat16*)sym(g_wgl);
    __nv_bfloat16* wuh = (__nv_bfloat16*)sym(g_wuh);
    __nv_bfloat16* wul = (__nv_bfloat16*)sym(g_wul);
    __nv_bfloat16* wdh = (__nv_bfloat16*)sym(g_wdh);
    __nv_bfloat16* wdl = (__nv_bfloat16*)sym(g_wdl);
    __nv_bfloat16* sgh = (__nv_bfloat16*)sym(g_sgh);
    __nv_bfloat16* sgl = (__nv_bfloat16*)sym(g_sgl);
    __nv_bfloat16* suh = (__nv_bfloat16*)sym(g_suh);
    __nv_bfloat16* sul = (__nv_bfloat16*)sym(g_sul);
    __nv_bfloat16* sdh = (__nv_bfloat16*)sym(g_sdh);
    __nv_bfloat16* sdl = (__nv_bfloat16*)sym(g_sdl);
    __nv_bfloat16* hrh = (__nv_bfloat16*)sym(g_hrh);
    __nv_bfloat16* hrl = (__nv_bfloat16*)sym(g_hrl);
    __nv_bfloat16* hsh = (__nv_bfloat16*)sym(g_hsh);
    __nv_bfloat16* hsl = (__nv_bfloat16*)sym(g_hsl);
    float*         Yp  = (float*)sym(g_Y);

    const int SMF = 3 * STAGE_F;   // 147456
    const int SMD = 3 * STAGE_D;   // 196608
    cudaFuncSetAttribute(mma_fused<false, false>,
                         cudaFuncAttributeMaxDynamicSharedMemorySize, SMF);
    cudaFuncSetAttribute(mma_fused<true, true>,
                         cudaFuncAttributeMaxDynamicSharedMemorySize, SMF);
    cudaFuncSetAttribute(mma_down<false>,
                         cudaFuncAttributeMaxDynamicSharedMemorySize, SMD);
    cudaFuncSetAttribute(mma_down<true>,
                         cudaFuncAttributeMaxDynamicSharedMemorySize, SMD);

    // Launch order puts the fused shared GEMM 6th so ncu (-s 5 -c 1) profiles it.
    // 1: x split
    convert_x_kernel<<<(T_TOKENS * H_DIM) / 1024, 256>>>(x, xh, xl);
    // 2-4: shared weight transposes
    transpose_conv<<<dim3(SI_DIM / 32, H_DIM / 32, 1), dim3(32, 8)>>>(
        sg, sgh, sgl, H_DIM, SI_DIM);
    transpose_conv<<<dim3(SI_DIM / 32, H_DIM / 32, 1), dim3(32, 8)>>>(
        su, suh, sul, H_DIM, SI_DIM);
    transpose_conv<<<dim3(H_DIM / 32, SI_DIM / 32, 1), dim3(32, 8)>>>(
        sd, sdh, sdl, SI_DIM, H_DIM);
    // 5: routing init
    zero_kernel<<<1, 32>>>();
    // 6: fused shared gate+up -> swiglu acts  (ncu target)
    mma_fused<false, false>
        <<<dim3(SI_DIM / 128, T_TOKENS / 128, 1), 256, SMF>>>(
            xh, xl, sgh, sgl, suh, sul, hsh, hsl, H_DIM, SI_DIM, T_TOKENS);
    // 7-9: routing
    route_kernel<<<T_TOKENS / 256, 256>>>();
    scan_kernel<<<1, 1>>>();
    scatter_kernel<<<T_TOKENS / 256, 256>>>();
    // 10-12: expert weight transposes
    transpose_conv<<<dim3(I_DIM / 32, H_DIM / 32, E_NUM), dim3(32, 8)>>>(
        w_gate, wgh, wgl, H_DIM, I_DIM);
    transpose_conv<<<dim3(I_DIM / 32, H_DIM / 32, E_NUM), dim3(32, 8)>>>(
        w_up, wuh, wul, H_DIM, I_DIM);
    transpose_conv<<<dim3(H_DIM / 32, I_DIM / 32, E_NUM), dim3(32, 8)>>>(
        w_down, wdh, wdl, I_DIM, H_DIM);
    // 13: fused routed gate+up (gathered)
    mma_fused<true, true>
        <<<dim3(I_DIM / 128, SLOTS / 128, E_NUM), 256, SMF>>>(
            xh, xl, wgh, wgl, wuh, wul, hrh, hrl, H_DIM, I_DIM, 0);
    // 14: shared down -> out (full overwrite)
    mma_down<false>
        <<<dim3(H_DIM / 128, T_TOKENS / 128, 1), 256, SMD>>>(
            hsh, hsl, sdh, sdl, out, SI_DIM, H_DIM, T_TOKENS);
    // 15: routed down -> Y
    mma_down<true>
        <<<dim3(H_DIM / 128, SLOTS / 128, E_NUM), 256, SMD>>>(
            hrh, hrl, wdh, wdl, Yp, I_DIM, H_DIM, 0);
    // 16: combine
    combine_kernel<<<dim3(H_DIM / 1024, T_TOKENS), 256>>>(out);
}